// round 1
// baseline (speedup 1.0000x reference)
#include <cuda_runtime.h>
#include <cstddef>

#define TSEQ 912
#define NB   512
#define HID  128
#define G4   512   // 4*H

typedef unsigned long long ull;

// ---------------- device scratch (static, allowed) ----------------
__device__ float g_xg[(size_t)TSEQ * G4 * NB];      // [t][gate][batch]  956 MB
__device__ float g_bufA[(size_t)NB * TSEQ * HID];   // [b][t][u]
__device__ float g_bufB[(size_t)NB * TSEQ * HID];
__device__ float g_hN[4 * NB * HID];                // [layer][b][u]

// ---------------- f32x2 helpers ----------------
__device__ __forceinline__ ull pack2(float lo, float hi) {
    ull r;
    asm("mov.b64 %0, {%1, %2};" : "=l"(r)
        : "r"(__float_as_uint(lo)), "r"(__float_as_uint(hi)));
    return r;
}
__device__ __forceinline__ float2 unpack2(ull v) {
    unsigned lo, hi;
    asm("mov.b64 {%0, %1}, %2;" : "=r"(lo), "=r"(hi) : "l"(v));
    return make_float2(__uint_as_float(lo), __uint_as_float(hi));
}
__device__ __forceinline__ void fma2(ull& d, ull a, ull b) {
    asm("fma.rn.f32x2 %0, %1, %2, %0;" : "+l"(d) : "l"(a), "l"(b));
}

// ---------------- activations ----------------
__device__ __forceinline__ float sigx(float x) {
    x = fminf(fmaxf(x, -30.f), 30.f);
    return __fdividef(1.f, 1.f + __expf(-x));
}
__device__ __forceinline__ float tanhx(float x) {
    x = fminf(fmaxf(x, -15.f), 15.f);
    float e = __expf(2.f * x);
    return __fdividef(e - 1.f, e + 1.f);
}

// =====================================================================
// Precompute: xg[t][g][b] = in[b][t][:] . Wih[g][:] + bih[g] + bhh[g]
// 512 threads, thread j owns gate j. Weights: k<KREG in regs (paired),
// k>=KREG in smem. Processes 8 (b,t)-rows per tile.
// =====================================================================
template<int K>
__global__ __launch_bounds__(512, 1)
void precompute_kernel(const float* __restrict__ xext, int insel,
                       const float* __restrict__ Wih,
                       const float* __restrict__ bih,
                       const float* __restrict__ bhh)
{
    extern __shared__ float sm[];
    constexpr int KREG = (K < 64) ? K : 64;
    constexpr int KSM  = K - KREG;
    ull*   wsp = (ull*)sm;                      // [KSM/2][512]
    float* xt  = sm + (KSM / 2) * 512 * 2;      // [8][K]

    const int j = threadIdx.x;
    const float* in = (K == 32) ? xext : (insel ? g_bufB : g_bufA);

    ull wregp[KREG / 2];
#pragma unroll
    for (int kk = 0; kk < KREG / 2; kk++)
        wregp[kk] = pack2(Wih[j * K + 2 * kk], Wih[j * K + 2 * kk + 1]);
#pragma unroll
    for (int kk = 0; kk < KSM / 2; kk++)
        wsp[kk * 512 + j] = pack2(Wih[j * K + KREG + 2 * kk],
                                  Wih[j * K + KREG + 2 * kk + 1]);
    const float bsum = bih[j] + bhh[j];
    __syncthreads();

    const int NT = TSEQ * (NB / 8);
    for (int tile = blockIdx.x; tile < NT; tile += gridDim.x) {
        const int t  = tile >> 6;          // tile / 64
        const int b0 = (tile & 63) << 3;   // 8 batch rows
        __syncthreads();
#pragma unroll
        for (int p = 0; p < (8 * K + 511) / 512; p++) {
            int idx = j + p * 512;
            if (idx < 8 * K) {
                int r = idx / K, k = idx % K;
                xt[r * K + k] = in[((size_t)(b0 + r) * TSEQ + t) * K + k];
            }
        }
        __syncthreads();

        ull acc[8] = {0, 0, 0, 0, 0, 0, 0, 0};
#pragma unroll
        for (int kq = 0; kq < KREG / 4; kq++) {
            ull w0 = wregp[2 * kq], w1 = wregp[2 * kq + 1];
#pragma unroll
            for (int r = 0; r < 8; r++) {
                ulonglong2 xv = *(const ulonglong2*)&xt[r * K + 4 * kq];
                fma2(acc[r], xv.x, w0);
                fma2(acc[r], xv.y, w1);
            }
        }
        if (KSM > 0) {
#pragma unroll
            for (int kq = 0; kq < KSM / 4; kq++) {
                ull w0 = wsp[(2 * kq) * 512 + j];
                ull w1 = wsp[(2 * kq + 1) * 512 + j];
#pragma unroll
                for (int r = 0; r < 8; r++) {
                    ulonglong2 xv = *(const ulonglong2*)&xt[r * K + KREG + 4 * kq];
                    fma2(acc[r], xv.x, w0);
                    fma2(acc[r], xv.y, w1);
                }
            }
        }
        float v[8];
#pragma unroll
        for (int r = 0; r < 8; r++) {
            float2 f = unpack2(acc[r]);
            v[r] = bsum + f.x + f.y;
        }
        float* dst = &g_xg[(size_t)(t * G4 + j) * NB + b0];
        *(float4*)(dst)     = make_float4(v[0], v[1], v[2], v[3]);
        *(float4*)(dst + 4) = make_float4(v[4], v[5], v[6], v[7]);
    }
}

// =====================================================================
// Recurrent: one block per 4 batch rows, 912 steps.
// Thread j owns gate j (phase 1) and (u = j&127, b = j>>7) (phase 2).
// =====================================================================
__global__ __launch_bounds__(512, 1)
void recurrent_kernel(const float* __restrict__ Whh, int outsel, int layer)
{
    extern __shared__ float sm[];
    ull*   wsp  = (ull*)sm;        // [32][512] = 128 KB   (k = 64..127, paired)
    float* h_s  = sm + 32768;      // [4][128]
    float* gact = h_s + 512;       // [4][512]

    const int j  = threadIdx.x;
    const int b0 = blockIdx.x * 4;
    float* out = outsel ? g_bufB : g_bufA;

    ull wregp[32];
#pragma unroll
    for (int kk = 0; kk < 32; kk++)
        wregp[kk] = pack2(Whh[j * 128 + 2 * kk], Whh[j * 128 + 2 * kk + 1]);
#pragma unroll
    for (int kk = 0; kk < 32; kk++)
        wsp[kk * 512 + j] = pack2(Whh[j * 128 + 64 + 2 * kk],
                                  Whh[j * 128 + 64 + 2 * kk + 1]);
    h_s[j & 511] = 0.f;            // zero all 512 h-state slots
    const int u  = j & 127;
    const int bb = j >> 7;
    const int gt = j >> 7;         // 0:i 1:f 2:g(tanh) 3:o
    float c = 0.f;
    __syncthreads();

    const int xbase = j * NB + b0;
    float4 xc = *(const float4*)&g_xg[xbase];   // t = 0 (prefetched)

    for (int t = 0; t < TSEQ; t++) {
        float4 xn = make_float4(0.f, 0.f, 0.f, 0.f);
        if (t + 1 < TSEQ)
            xn = *(const float4*)&g_xg[(size_t)(t + 1) * (G4 * NB) + xbase];

        // ---- phase 1: gate pre-activations, 4 batch rows, vertical f32x2 ----
        ull a0 = 0, a1 = 0, a2 = 0, a3 = 0;
#pragma unroll
        for (int kq = 0; kq < 16; kq++) {
            ull w0 = wregp[2 * kq], w1 = wregp[2 * kq + 1];
            ulonglong2 h0 = *(const ulonglong2*)&h_s[0 * 128 + 4 * kq];
            ulonglong2 h1 = *(const ulonglong2*)&h_s[1 * 128 + 4 * kq];
            ulonglong2 h2 = *(const ulonglong2*)&h_s[2 * 128 + 4 * kq];
            ulonglong2 h3 = *(const ulonglong2*)&h_s[3 * 128 + 4 * kq];
            fma2(a0, h0.x, w0); fma2(a0, h0.y, w1);
            fma2(a1, h1.x, w0); fma2(a1, h1.y, w1);
            fma2(a2, h2.x, w0); fma2(a2, h2.y, w1);
            fma2(a3, h3.x, w0); fma2(a3, h3.y, w1);
        }
#pragma unroll
        for (int kq = 0; kq < 16; kq++) {
            ull w0 = wsp[(2 * kq) * 512 + j];
            ull w1 = wsp[(2 * kq + 1) * 512 + j];
            ulonglong2 h0 = *(const ulonglong2*)&h_s[0 * 128 + 64 + 4 * kq];
            ulonglong2 h1 = *(const ulonglong2*)&h_s[1 * 128 + 64 + 4 * kq];
            ulonglong2 h2 = *(const ulonglong2*)&h_s[2 * 128 + 64 + 4 * kq];
            ulonglong2 h3 = *(const ulonglong2*)&h_s[3 * 128 + 64 + 4 * kq];
            fma2(a0, h0.x, w0); fma2(a0, h0.y, w1);
            fma2(a1, h1.x, w0); fma2(a1, h1.y, w1);
            fma2(a2, h2.x, w0); fma2(a2, h2.y, w1);
            fma2(a3, h3.x, w0); fma2(a3, h3.y, w1);
        }
        float2 f0 = unpack2(a0), f1 = unpack2(a1), f2 = unpack2(a2), f3 = unpack2(a3);
        float v0 = xc.x + f0.x + f0.y;
        float v1 = xc.y + f1.x + f1.y;
        float v2 = xc.z + f2.x + f2.y;
        float v3 = xc.w + f3.x + f3.y;
        if (gt == 2) { v0 = tanhx(v0); v1 = tanhx(v1); v2 = tanhx(v2); v3 = tanhx(v3); }
        else         { v0 = sigx(v0);  v1 = sigx(v1);  v2 = sigx(v2);  v3 = sigx(v3);  }
        gact[0 * 512 + j] = v0;
        gact[1 * 512 + j] = v1;
        gact[2 * 512 + j] = v2;
        gact[3 * 512 + j] = v3;
        __syncthreads();

        // ---- phase 2: c/h update for (u, bb) ----
        float iv = gact[bb * 512 + u];
        float fv = gact[bb * 512 + 128 + u];
        float gv = gact[bb * 512 + 256 + u];
        float ov = gact[bb * 512 + 384 + u];
        c = fv * c + iv * gv;
        float h = ov * tanhx(c);
        h_s[bb * 128 + u] = h;
        out[((size_t)(b0 + bb) * TSEQ + t) * HID + u] = h;
        if (t == TSEQ - 1)
            g_hN[layer * (NB * HID) + (b0 + bb) * HID + u] = h;
        __syncthreads();
        xc = xn;
    }
}

// =====================================================================
// Heads: hN [4,512,128] -> (opt, tp, sl, lot), each [4,512,4]
// =====================================================================
__global__ void heads_kernel(
    const float* __restrict__ Wopt, const float* __restrict__ bopt,
    const float* __restrict__ Wlot, const float* __restrict__ blot,
    const float* __restrict__ Wtp,  const float* __restrict__ btp,
    const float* __restrict__ Wsl,  const float* __restrict__ bsl,
    float* __restrict__ outp)
{
    int tid = blockIdx.x * blockDim.x + threadIdx.x;
    if (tid >= 4 * 2048) return;
    int head = tid >> 11;        // 0:opt 1:tp 2:sl 3:lot
    int r    = tid & 2047;       // layer*512 + batch
    const float* W; const float* b;
    if      (head == 0) { W = Wopt; b = bopt; }
    else if (head == 1) { W = Wtp;  b = btp;  }
    else if (head == 2) { W = Wsl;  b = bsl;  }
    else                { W = Wlot; b = blot; }

    float y0 = b[0], y1 = b[1], y2 = b[2], y3 = b[3];
    const float4* hv = (const float4*)&g_hN[r * HID];
    const float4* w0 = (const float4*)&W[0];
    const float4* w1 = (const float4*)&W[128];
    const float4* w2 = (const float4*)&W[256];
    const float4* w3 = (const float4*)&W[384];
#pragma unroll 8
    for (int q = 0; q < 32; q++) {
        float4 h = hv[q];
        float4 a = w0[q]; y0 += h.x*a.x + h.y*a.y + h.z*a.z + h.w*a.w;
        float4 bq = w1[q]; y1 += h.x*bq.x + h.y*bq.y + h.z*bq.z + h.w*bq.w;
        float4 cq = w2[q]; y2 += h.x*cq.x + h.y*cq.y + h.z*cq.z + h.w*cq.w;
        float4 dq = w3[q]; y3 += h.x*dq.x + h.y*dq.y + h.z*dq.z + h.w*dq.w;
    }
    float o0, o1, o2, o3;
    if (head == 0) {
        float m = fmaxf(fmaxf(y0, y1), fmaxf(y2, y3));
        float e0 = __expf(y0 - m), e1 = __expf(y1 - m),
              e2 = __expf(y2 - m), e3 = __expf(y3 - m);
        float s = e0 + e1 + e2 + e3;
        float p0 = e0 / s, p1 = e1 / s, p2 = e2 / s, p3 = e3 / s;
        m = fmaxf(fmaxf(p0, p1), fmaxf(p2, p3));
        e0 = __expf(p0 - m); e1 = __expf(p1 - m);
        e2 = __expf(p2 - m); e3 = __expf(p3 - m);
        s = e0 + e1 + e2 + e3;
        o0 = e0 / s; o1 = e1 / s; o2 = e2 / s; o3 = e3 / s;
    } else {
        o0 = sigx(sigx(y0)); o1 = sigx(sigx(y1));
        o2 = sigx(sigx(y2)); o3 = sigx(sigx(y3));
    }
    float* dst = outp + head * 8192 + r * 4;
    dst[0] = o0; dst[1] = o1; dst[2] = o2; dst[3] = o3;
}

// =====================================================================
extern "C" void kernel_launch(void* const* d_in, const int* in_sizes, int n_in,
                              void* d_out, int out_size)
{
    const float* x      = (const float*)d_in[0];
    const float* Wih0   = (const float*)d_in[1];
    const float* Whh0   = (const float*)d_in[2];
    const float* bih0   = (const float*)d_in[3];
    const float* bhh0   = (const float*)d_in[4];
    const float* Wih123 = (const float*)d_in[5];
    const float* Whh123 = (const float*)d_in[6];
    const float* bih123 = (const float*)d_in[7];
    const float* bhh123 = (const float*)d_in[8];
    const float* Wopt   = (const float*)d_in[9];
    const float* bopt   = (const float*)d_in[10];
    const float* Wlot   = (const float*)d_in[11];
    const float* blot   = (const float*)d_in[12];
    const float* Wtp    = (const float*)d_in[13];
    const float* btp    = (const float*)d_in[14];
    const float* Wsl    = (const float*)d_in[15];
    const float* bsl    = (const float*)d_in[16];
    float* outp = (float*)d_out;

    const int SM_PRE128 = 32 * 512 * 8 + 8 * 128 * 4;            // 135168
    const int SM_PRE32  = 8 * 32 * 4;                            // 1024
    const int SM_REC    = 32 * 512 * 8 + 512 * 4 + 2048 * 4;     // 141312

    cudaFuncSetAttribute(precompute_kernel<128>,
                         cudaFuncAttributeMaxDynamicSharedMemorySize, SM_PRE128);
    cudaFuncSetAttribute(recurrent_kernel,
                         cudaFuncAttributeMaxDynamicSharedMemorySize, SM_REC);

    // layer 0
    precompute_kernel<32><<<148, 512, SM_PRE32>>>(x, 0, Wih0, bih0, bhh0);
    recurrent_kernel<<<128, 512, SM_REC>>>(Whh0, /*out=A*/0, /*layer*/0);
    // layer 1 (in A -> out B)
    precompute_kernel<128><<<148, 512, SM_PRE128>>>(nullptr, 0,
        Wih123 + 0 * G4 * HID, bih123 + 0 * G4, bhh123 + 0 * G4);
    recurrent_kernel<<<128, 512, SM_REC>>>(Whh123 + 0 * G4 * HID, 1, 1);
    // layer 2 (in B -> out A)
    precompute_kernel<128><<<148, 512, SM_PRE128>>>(nullptr, 1,
        Wih123 + 1 * G4 * HID, bih123 + 1 * G4, bhh123 + 1 * G4);
    recurrent_kernel<<<128, 512, SM_REC>>>(Whh123 + 1 * G4 * HID, 0, 2);
    // layer 3 (in A -> out B)
    precompute_kernel<128><<<148, 512, SM_PRE128>>>(nullptr, 0,
        Wih123 + 2 * G4 * HID, bih123 + 2 * G4, bhh123 + 2 * G4);
    recurrent_kernel<<<128, 512, SM_REC>>>(Whh123 + 2 * G4 * HID, 1, 3);
    // heads
    heads_kernel<<<(4 * 2048 + 255) / 256, 256>>>(
        Wopt, bopt, Wlot, blot, Wtp, btp, Wsl, bsl, outp);
}

// round 2
// speedup vs baseline: 1.0003x; 1.0003x over previous
#include <cuda_runtime.h>
#include <cstddef>

#define TSEQ 912
#define NB   512
#define HID  128
#define G4   512   // 4*H

typedef unsigned long long ull;

// ---------------- device scratch (static, allowed) ----------------
__device__ float g_xg[(size_t)TSEQ * G4 * NB];      // [t][gate][batch]  956 MB
__device__ float g_bufA[(size_t)NB * TSEQ * HID];   // [b][t][u]
__device__ float g_bufB[(size_t)NB * TSEQ * HID];
__device__ float g_hN[4 * NB * HID];                // [layer][b][u]

// ---------------- f32x2 helpers ----------------
__device__ __forceinline__ ull pack2(float lo, float hi) {
    ull r;
    asm("mov.b64 %0, {%1, %2};" : "=l"(r)
        : "r"(__float_as_uint(lo)), "r"(__float_as_uint(hi)));
    return r;
}
__device__ __forceinline__ float2 unpack2(ull v) {
    unsigned lo, hi;
    asm("mov.b64 {%0, %1}, %2;" : "=r"(lo), "=r"(hi) : "l"(v));
    return make_float2(__uint_as_float(lo), __uint_as_float(hi));
}
__device__ __forceinline__ void fma2(ull& d, ull a, ull b) {
    asm("fma.rn.f32x2 %0, %1, %2, %0;" : "+l"(d) : "l"(a), "l"(b));
}

// ---------------- activations ----------------
__device__ __forceinline__ float sigx(float x) {
    x = fminf(fmaxf(x, -30.f), 30.f);
    return __fdividef(1.f, 1.f + __expf(-x));
}
__device__ __forceinline__ float tanhx(float x) {
    x = fminf(fmaxf(x, -15.f), 15.f);
    float e = __expf(2.f * x);
    return __fdividef(e - 1.f, e + 1.f);
}

// =====================================================================
// Precompute: xg[t][g][b] = in[b][t][:] . Wih[g][:] + bih[g] + bhh[g]
// 512 threads, thread j owns gate j. Weights: k<KREG in regs (paired),
// k>=KREG in smem. Processes 8 (b,t)-rows per tile.
// =====================================================================
template<int K>
__global__ __launch_bounds__(512, 1)
void precompute_kernel(const float* __restrict__ xext, int insel,
                       const float* __restrict__ Wih,
                       const float* __restrict__ bih,
                       const float* __restrict__ bhh)
{
    extern __shared__ float sm[];
    constexpr int KREG = (K < 64) ? K : 64;
    constexpr int KSM  = K - KREG;
    ull*   wsp = (ull*)sm;                      // [KSM/2][512]
    float* xt  = sm + (KSM / 2) * 512 * 2;      // [8][K]

    const int j = threadIdx.x;
    const float* in = (K == 32) ? xext : (insel ? g_bufB : g_bufA);

    ull wregp[KREG / 2];
#pragma unroll
    for (int kk = 0; kk < KREG / 2; kk++)
        wregp[kk] = pack2(Wih[j * K + 2 * kk], Wih[j * K + 2 * kk + 1]);
#pragma unroll
    for (int kk = 0; kk < KSM / 2; kk++)
        wsp[kk * 512 + j] = pack2(Wih[j * K + KREG + 2 * kk],
                                  Wih[j * K + KREG + 2 * kk + 1]);
    const float bsum = bih[j] + bhh[j];
    __syncthreads();

    const int NT = TSEQ * (NB / 8);
    for (int tile = blockIdx.x; tile < NT; tile += gridDim.x) {
        const int t  = tile >> 6;          // tile / 64
        const int b0 = (tile & 63) << 3;   // 8 batch rows
        __syncthreads();
#pragma unroll
        for (int p = 0; p < (8 * K + 511) / 512; p++) {
            int idx = j + p * 512;
            if (idx < 8 * K) {
                int r = idx / K, k = idx % K;
                xt[r * K + k] = in[((size_t)(b0 + r) * TSEQ + t) * K + k];
            }
        }
        __syncthreads();

        ull acc[8] = {0, 0, 0, 0, 0, 0, 0, 0};
#pragma unroll
        for (int kq = 0; kq < KREG / 4; kq++) {
            ull w0 = wregp[2 * kq], w1 = wregp[2 * kq + 1];
#pragma unroll
            for (int r = 0; r < 8; r++) {
                ulonglong2 xv = *(const ulonglong2*)&xt[r * K + 4 * kq];
                fma2(acc[r], xv.x, w0);
                fma2(acc[r], xv.y, w1);
            }
        }
        if (KSM > 0) {
#pragma unroll
            for (int kq = 0; kq < KSM / 4; kq++) {
                ull w0 = wsp[(2 * kq) * 512 + j];
                ull w1 = wsp[(2 * kq + 1) * 512 + j];
#pragma unroll
                for (int r = 0; r < 8; r++) {
                    ulonglong2 xv = *(const ulonglong2*)&xt[r * K + KREG + 4 * kq];
                    fma2(acc[r], xv.x, w0);
                    fma2(acc[r], xv.y, w1);
                }
            }
        }
        float v[8];
#pragma unroll
        for (int r = 0; r < 8; r++) {
            float2 f = unpack2(acc[r]);
            v[r] = bsum + f.x + f.y;
        }
        float* dst = &g_xg[(size_t)(t * G4 + j) * NB + b0];
        *(float4*)(dst)     = make_float4(v[0], v[1], v[2], v[3]);
        *(float4*)(dst + 4) = make_float4(v[4], v[5], v[6], v[7]);
    }
}

// =====================================================================
// Recurrent: one block per 4 batch rows, 912 steps.
// Thread j owns gate j (phase 1) and (u = j&127, b = j>>7) (phase 2).
// =====================================================================
__global__ __launch_bounds__(512, 1)
void recurrent_kernel(const float* __restrict__ Whh, int outsel, int layer)
{
    extern __shared__ float sm[];
    ull*   wsp  = (ull*)sm;        // [32][512] = 128 KB   (k = 64..127, paired)
    float* h_s  = sm + 32768;      // [4][128]
    float* gact = h_s + 512;       // [4][512]

    const int j  = threadIdx.x;
    const int b0 = blockIdx.x * 4;
    float* out = outsel ? g_bufB : g_bufA;

    ull wregp[32];
#pragma unroll
    for (int kk = 0; kk < 32; kk++)
        wregp[kk] = pack2(Whh[j * 128 + 2 * kk], Whh[j * 128 + 2 * kk + 1]);
#pragma unroll
    for (int kk = 0; kk < 32; kk++)
        wsp[kk * 512 + j] = pack2(Whh[j * 128 + 64 + 2 * kk],
                                  Whh[j * 128 + 64 + 2 * kk + 1]);
    h_s[j & 511] = 0.f;            // zero all 512 h-state slots
    const int u  = j & 127;
    const int bb = j >> 7;
    const int gt = j >> 7;         // 0:i 1:f 2:g(tanh) 3:o
    float c = 0.f;
    __syncthreads();

    const int xbase = j * NB + b0;
    float4 xc = *(const float4*)&g_xg[xbase];   // t = 0 (prefetched)

    for (int t = 0; t < TSEQ; t++) {
        float4 xn = make_float4(0.f, 0.f, 0.f, 0.f);
        if (t + 1 < TSEQ)
            xn = *(const float4*)&g_xg[(size_t)(t + 1) * (G4 * NB) + xbase];

        // ---- phase 1: gate pre-activations, 4 batch rows, vertical f32x2 ----
        ull a0 = 0, a1 = 0, a2 = 0, a3 = 0;
#pragma unroll
        for (int kq = 0; kq < 16; kq++) {
            ull w0 = wregp[2 * kq], w1 = wregp[2 * kq + 1];
            ulonglong2 h0 = *(const ulonglong2*)&h_s[0 * 128 + 4 * kq];
            ulonglong2 h1 = *(const ulonglong2*)&h_s[1 * 128 + 4 * kq];
            ulonglong2 h2 = *(const ulonglong2*)&h_s[2 * 128 + 4 * kq];
            ulonglong2 h3 = *(const ulonglong2*)&h_s[3 * 128 + 4 * kq];
            fma2(a0, h0.x, w0); fma2(a0, h0.y, w1);
            fma2(a1, h1.x, w0); fma2(a1, h1.y, w1);
            fma2(a2, h2.x, w0); fma2(a2, h2.y, w1);
            fma2(a3, h3.x, w0); fma2(a3, h3.y, w1);
        }
#pragma unroll
        for (int kq = 0; kq < 16; kq++) {
            ull w0 = wsp[(2 * kq) * 512 + j];
            ull w1 = wsp[(2 * kq + 1) * 512 + j];
            ulonglong2 h0 = *(const ulonglong2*)&h_s[0 * 128 + 64 + 4 * kq];
            ulonglong2 h1 = *(const ulonglong2*)&h_s[1 * 128 + 64 + 4 * kq];
            ulonglong2 h2 = *(const ulonglong2*)&h_s[2 * 128 + 64 + 4 * kq];
            ulonglong2 h3 = *(const ulonglong2*)&h_s[3 * 128 + 64 + 4 * kq];
            fma2(a0, h0.x, w0); fma2(a0, h0.y, w1);
            fma2(a1, h1.x, w0); fma2(a1, h1.y, w1);
            fma2(a2, h2.x, w0); fma2(a2, h2.y, w1);
            fma2(a3, h3.x, w0); fma2(a3, h3.y, w1);
        }
        float2 f0 = unpack2(a0), f1 = unpack2(a1), f2 = unpack2(a2), f3 = unpack2(a3);
        float v0 = xc.x + f0.x + f0.y;
        float v1 = xc.y + f1.x + f1.y;
        float v2 = xc.z + f2.x + f2.y;
        float v3 = xc.w + f3.x + f3.y;
        if (gt == 2) { v0 = tanhx(v0); v1 = tanhx(v1); v2 = tanhx(v2); v3 = tanhx(v3); }
        else         { v0 = sigx(v0);  v1 = sigx(v1);  v2 = sigx(v2);  v3 = sigx(v3);  }
        gact[0 * 512 + j] = v0;
        gact[1 * 512 + j] = v1;
        gact[2 * 512 + j] = v2;
        gact[3 * 512 + j] = v3;
        __syncthreads();

        // ---- phase 2: c/h update for (u, bb) ----
        float iv = gact[bb * 512 + u];
        float fv = gact[bb * 512 + 128 + u];
        float gv = gact[bb * 512 + 256 + u];
        float ov = gact[bb * 512 + 384 + u];
        c = fv * c + iv * gv;
        float h = ov * tanhx(c);
        h_s[bb * 128 + u] = h;
        out[((size_t)(b0 + bb) * TSEQ + t) * HID + u] = h;
        if (t == TSEQ - 1)
            g_hN[layer * (NB * HID) + (b0 + bb) * HID + u] = h;
        __syncthreads();
        xc = xn;
    }
}

// =====================================================================
// Heads: hN [4,512,128] -> (opt, tp, sl, lot), each [4,512,4]
// =====================================================================
__global__ void heads_kernel(
    const float* __restrict__ Wopt, const float* __restrict__ bopt,
    const float* __restrict__ Wlot, const float* __restrict__ blot,
    const float* __restrict__ Wtp,  const float* __restrict__ btp,
    const float* __restrict__ Wsl,  const float* __restrict__ bsl,
    float* __restrict__ outp)
{
    int tid = blockIdx.x * blockDim.x + threadIdx.x;
    if (tid >= 4 * 2048) return;
    int head = tid >> 11;        // 0:opt 1:tp 2:sl 3:lot
    int r    = tid & 2047;       // layer*512 + batch
    const float* W; const float* b;
    if      (head == 0) { W = Wopt; b = bopt; }
    else if (head == 1) { W = Wtp;  b = btp;  }
    else if (head == 2) { W = Wsl;  b = bsl;  }
    else                { W = Wlot; b = blot; }

    float y0 = b[0], y1 = b[1], y2 = b[2], y3 = b[3];
    const float4* hv = (const float4*)&g_hN[r * HID];
    const float4* w0 = (const float4*)&W[0];
    const float4* w1 = (const float4*)&W[128];
    const float4* w2 = (const float4*)&W[256];
    const float4* w3 = (const float4*)&W[384];
#pragma unroll 8
    for (int q = 0; q < 32; q++) {
        float4 h = hv[q];
        float4 a = w0[q]; y0 += h.x*a.x + h.y*a.y + h.z*a.z + h.w*a.w;
        float4 bq = w1[q]; y1 += h.x*bq.x + h.y*bq.y + h.z*bq.z + h.w*bq.w;
        float4 cq = w2[q]; y2 += h.x*cq.x + h.y*cq.y + h.z*cq.z + h.w*cq.w;
        float4 dq = w3[q]; y3 += h.x*dq.x + h.y*dq.y + h.z*dq.z + h.w*dq.w;
    }
    float o0, o1, o2, o3;
    if (head == 0) {
        float m = fmaxf(fmaxf(y0, y1), fmaxf(y2, y3));
        float e0 = __expf(y0 - m), e1 = __expf(y1 - m),
              e2 = __expf(y2 - m), e3 = __expf(y3 - m);
        float s = e0 + e1 + e2 + e3;
        float p0 = e0 / s, p1 = e1 / s, p2 = e2 / s, p3 = e3 / s;
        m = fmaxf(fmaxf(p0, p1), fmaxf(p2, p3));
        e0 = __expf(p0 - m); e1 = __expf(p1 - m);
        e2 = __expf(p2 - m); e3 = __expf(p3 - m);
        s = e0 + e1 + e2 + e3;
        o0 = e0 / s; o1 = e1 / s; o2 = e2 / s; o3 = e3 / s;
    } else {
        o0 = sigx(sigx(y0)); o1 = sigx(sigx(y1));
        o2 = sigx(sigx(y2)); o3 = sigx(sigx(y3));
    }
    float* dst = outp + head * 8192 + r * 4;
    dst[0] = o0; dst[1] = o1; dst[2] = o2; dst[3] = o3;
}

// =====================================================================
extern "C" void kernel_launch(void* const* d_in, const int* in_sizes, int n_in,
                              void* d_out, int out_size)
{
    const float* x      = (const float*)d_in[0];
    const float* Wih0   = (const float*)d_in[1];
    const float* Whh0   = (const float*)d_in[2];
    const float* bih0   = (const float*)d_in[3];
    const float* bhh0   = (const float*)d_in[4];
    const float* Wih123 = (const float*)d_in[5];
    const float* Whh123 = (const float*)d_in[6];
    const float* bih123 = (const float*)d_in[7];
    const float* bhh123 = (const float*)d_in[8];
    const float* Wopt   = (const float*)d_in[9];
    const float* bopt   = (const float*)d_in[10];
    const float* Wlot   = (const float*)d_in[11];
    const float* blot   = (const float*)d_in[12];
    const float* Wtp    = (const float*)d_in[13];
    const float* btp    = (const float*)d_in[14];
    const float* Wsl    = (const float*)d_in[15];
    const float* bsl    = (const float*)d_in[16];
    float* outp = (float*)d_out;

    const int SM_PRE128 = 32 * 512 * 8 + 8 * 128 * 4;            // 135168
    const int SM_PRE32  = 8 * 32 * 4;                            // 1024
    const int SM_REC    = 32 * 512 * 8 + 512 * 4 + 2048 * 4;     // 141312

    cudaFuncSetAttribute(precompute_kernel<128>,
                         cudaFuncAttributeMaxDynamicSharedMemorySize, SM_PRE128);
    cudaFuncSetAttribute(recurrent_kernel,
                         cudaFuncAttributeMaxDynamicSharedMemorySize, SM_REC);

    // layer 0
    precompute_kernel<32><<<148, 512, SM_PRE32>>>(x, 0, Wih0, bih0, bhh0);
    recurrent_kernel<<<128, 512, SM_REC>>>(Whh0, /*out=A*/0, /*layer*/0);
    // layer 1 (in A -> out B)
    precompute_kernel<128><<<148, 512, SM_PRE128>>>(nullptr, 0,
        Wih123 + 0 * G4 * HID, bih123 + 0 * G4, bhh123 + 0 * G4);
    recurrent_kernel<<<128, 512, SM_REC>>>(Whh123 + 0 * G4 * HID, 1, 1);
    // layer 2 (in B -> out A)
    precompute_kernel<128><<<148, 512, SM_PRE128>>>(nullptr, 1,
        Wih123 + 1 * G4 * HID, bih123 + 1 * G4, bhh123 + 1 * G4);
    recurrent_kernel<<<128, 512, SM_REC>>>(Whh123 + 1 * G4 * HID, 0, 2);
    // layer 3 (in A -> out B)
    precompute_kernel<128><<<148, 512, SM_PRE128>>>(nullptr, 0,
        Wih123 + 2 * G4 * HID, bih123 + 2 * G4, bhh123 + 2 * G4);
    recurrent_kernel<<<128, 512, SM_REC>>>(Whh123 + 2 * G4 * HID, 1, 3);
    // heads
    heads_kernel<<<(4 * 2048 + 255) / 256, 256>>>(
        Wopt, bopt, Wlot, blot, Wtp, btp, Wsl, bsl, outp);
}

// round 3
// speedup vs baseline: 1.0999x; 1.0995x over previous
#include <cuda_runtime.h>
#include <cstddef>

#define TSEQ 912
#define NB   512
#define HID  128
#define G4   512   // 4*H

typedef unsigned long long ull;

// ---------------- device scratch (static, allowed) ----------------
__device__ float g_xg[(size_t)TSEQ * G4 * NB];      // [t][gate][batch]
__device__ float g_bufA[(size_t)NB * TSEQ * HID];   // [b][t][u]
__device__ float g_bufB[(size_t)NB * TSEQ * HID];
__device__ float g_hN[4 * NB * HID];                // [layer][b][u]

// ---------------- f32x2 helpers ----------------
__device__ __forceinline__ ull pack2(float lo, float hi) {
    ull r;
    asm("mov.b64 %0, {%1, %2};" : "=l"(r)
        : "r"(__float_as_uint(lo)), "r"(__float_as_uint(hi)));
    return r;
}
__device__ __forceinline__ float2 unpack2(ull v) {
    unsigned lo, hi;
    asm("mov.b64 {%0, %1}, %2;" : "=r"(lo), "=r"(hi) : "l"(v));
    return make_float2(__uint_as_float(lo), __uint_as_float(hi));
}
__device__ __forceinline__ void fma2(ull& d, ull a, ull b) {
    asm("fma.rn.f32x2 %0, %1, %2, %0;" : "+l"(d) : "l"(a), "l"(b));
}

// ---------------- activations ----------------
__device__ __forceinline__ float sigx(float x) {
    x = fminf(fmaxf(x, -30.f), 30.f);
    return __fdividef(1.f, 1.f + __expf(-x));
}
__device__ __forceinline__ float tanhx(float x) {
    x = fminf(fmaxf(x, -15.f), 15.f);
    float e = __expf(2.f * x);
    return __fdividef(e - 1.f, e + 1.f);
}

// ---------------- cp.async helpers ----------------
__device__ __forceinline__ unsigned smem_u32(const void* p) {
    return (unsigned)__cvta_generic_to_shared(p);
}
__device__ __forceinline__ void cpasync16(unsigned saddr, const void* gaddr) {
    asm volatile("cp.async.ca.shared.global [%0], [%1], 16;"
                 :: "r"(saddr), "l"(gaddr));
}
__device__ __forceinline__ void cpasync_commit() {
    asm volatile("cp.async.commit_group;");
}
__device__ __forceinline__ void cpasync_wait1() {
    asm volatile("cp.async.wait_group 1;");
}

// =====================================================================
// Precompute: xg[t][g][b] = in[b][t][:] . Wih[g][:] + bih[g] + bhh[g]
// =====================================================================
template<int K>
__global__ __launch_bounds__(512, 1)
void precompute_kernel(const float* __restrict__ xext, int insel,
                       const float* __restrict__ Wih,
                       const float* __restrict__ bih,
                       const float* __restrict__ bhh)
{
    extern __shared__ float sm[];
    constexpr int KREG = (K < 64) ? K : 64;
    constexpr int KSM  = K - KREG;
    ull*   wsp = (ull*)sm;                      // [KSM/2][512]
    float* xt  = sm + (KSM / 2) * 512 * 2;      // [8][K]

    const int j = threadIdx.x;
    const float* in = (K == 32) ? xext : (insel ? g_bufB : g_bufA);

    ull wregp[KREG / 2];
#pragma unroll
    for (int kk = 0; kk < KREG / 2; kk++)
        wregp[kk] = pack2(Wih[j * K + 2 * kk], Wih[j * K + 2 * kk + 1]);
#pragma unroll
    for (int kk = 0; kk < KSM / 2; kk++)
        wsp[kk * 512 + j] = pack2(Wih[j * K + KREG + 2 * kk],
                                  Wih[j * K + KREG + 2 * kk + 1]);
    const float bsum = bih[j] + bhh[j];
    __syncthreads();

    const int NT = TSEQ * (NB / 8);
    for (int tile = blockIdx.x; tile < NT; tile += gridDim.x) {
        const int t  = tile >> 6;
        const int b0 = (tile & 63) << 3;
        __syncthreads();
#pragma unroll
        for (int p = 0; p < (8 * K + 511) / 512; p++) {
            int idx = j + p * 512;
            if (idx < 8 * K) {
                int r = idx / K, k = idx % K;
                xt[r * K + k] = in[((size_t)(b0 + r) * TSEQ + t) * K + k];
            }
        }
        __syncthreads();

        ull acc[8] = {0, 0, 0, 0, 0, 0, 0, 0};
#pragma unroll
        for (int kq = 0; kq < KREG / 4; kq++) {
            ull w0 = wregp[2 * kq], w1 = wregp[2 * kq + 1];
#pragma unroll
            for (int r = 0; r < 8; r++) {
                ulonglong2 xv = *(const ulonglong2*)&xt[r * K + 4 * kq];
                fma2(acc[r], xv.x, w0);
                fma2(acc[r], xv.y, w1);
            }
        }
        if (KSM > 0) {
#pragma unroll
            for (int kq = 0; kq < KSM / 4; kq++) {
                ull w0 = wsp[(2 * kq) * 512 + j];
                ull w1 = wsp[(2 * kq + 1) * 512 + j];
#pragma unroll
                for (int r = 0; r < 8; r++) {
                    ulonglong2 xv = *(const ulonglong2*)&xt[r * K + KREG + 4 * kq];
                    fma2(acc[r], xv.x, w0);
                    fma2(acc[r], xv.y, w1);
                }
            }
        }
        float v[8];
#pragma unroll
        for (int r = 0; r < 8; r++) {
            float2 f = unpack2(acc[r]);
            v[r] = bsum + f.x + f.y;
        }
        float* dst = &g_xg[(size_t)(t * G4 + j) * NB + b0];
        *(float4*)(dst)     = make_float4(v[0], v[1], v[2], v[3]);
        *(float4*)(dst + 4) = make_float4(v[4], v[5], v[6], v[7]);
    }
}

// =====================================================================
// Recurrent kernel: one block per 4 batch rows, 912 steps.
// Phase 1: thread j -> gates (2*(j&255), 2*(j&255)+1), k-half ks=j>>8.
//   gate g0 weights in registers, gate g1 weights from smem.
//   k-split partials reduced through smem (ks=1 -> ks=0).
// Phase 2: thread j -> (row bb=j>>7, unit u=j&127) c/h update.
// xg staged into smem via cp.async double buffer.
// =====================================================================
__global__ __launch_bounds__(512, 1)
void recurrent_kernel(const float* __restrict__ Whh, int outsel, int layer)
{
    extern __shared__ char smraw[];
    ulonglong2* wsp2 = (ulonglong2*)smraw;                 // [16][512]  128 KB
    float* h_s  = (float*)(smraw + 131072);                // [4][128]     2 KB
    float* gact = h_s + 512;                               // [4][512]     8 KB
    float* red  = gact + 2048;                             // [4][512]     8 KB
    float* xgs  = red + 2048;                              // [2][512][4] 16 KB

    const int j   = threadIdx.x;
    const int jj  = j & 255;
    const int ks  = j >> 8;          // k-half: warps 0-7 -> 0, 8-15 -> 1
    const int g0  = 2 * jj;
    const int b0  = blockIdx.x * 4;
    float* out = outsel ? g_bufB : g_bufA;

    // gate g0 weights (this k-half) -> registers, pre-paired
    ull wr[32];
#pragma unroll
    for (int kk = 0; kk < 32; kk++)
        wr[kk] = pack2(Whh[g0 * 128 + ks * 64 + 2 * kk],
                       Whh[g0 * 128 + ks * 64 + 2 * kk + 1]);
    // gate g1 weights (this k-half) -> smem, pre-paired, 16B granules
#pragma unroll
    for (int kq = 0; kq < 16; kq++) {
        ulonglong2 wv;
        wv.x = pack2(Whh[(g0 + 1) * 128 + ks * 64 + 4 * kq],
                     Whh[(g0 + 1) * 128 + ks * 64 + 4 * kq + 1]);
        wv.y = pack2(Whh[(g0 + 1) * 128 + ks * 64 + 4 * kq + 2],
                     Whh[(g0 + 1) * 128 + ks * 64 + 4 * kq + 3]);
        wsp2[kq * 512 + j] = wv;
    }
    h_s[j] = 0.f;

    const int u  = j & 127;
    const int bb = j >> 7;
    const int gtype = jj >> 6;       // gate type of g0/g1: 0:i 1:f 2:g 3:o
    float c = 0.f;

    // prologue: stage xg[t=0] into buffer 0
    const unsigned xgs_s = smem_u32(xgs);
    cpasync16(xgs_s + (unsigned)j * 16, &g_xg[(size_t)j * NB + b0]);
    cpasync_commit();
    __syncthreads();

    const float* hsp = h_s + ks * 64;
    const ulonglong2* wbase = wsp2 + j;

    for (int t = 0; t < TSEQ; t++) {
        // prefetch xg[t+1] into the other buffer
        {
            int tn = (t + 1 < TSEQ) ? (t + 1) : t;
            unsigned dst = xgs_s + (unsigned)(((t + 1) & 1) * 2048 + j * 4) * 4;
            cpasync16(dst, &g_xg[((size_t)tn * G4 + j) * NB + b0]);
            cpasync_commit();
        }

        // ---- phase 1: partial gate pre-activations (2 gates x 4 rows x 64 k) ----
        ull a0 = 0, a1 = 0, a2 = 0, a3 = 0;   // gate g0, rows 0..3
        ull a4 = 0, a5 = 0, a6 = 0, a7 = 0;   // gate g1, rows 0..3
#pragma unroll
        for (int kq = 0; kq < 16; kq++) {
            ulonglong2 wv = wbase[kq * 512];
            ull w0 = wr[2 * kq], w1 = wr[2 * kq + 1];
            ulonglong2 h0 = *(const ulonglong2*)(hsp + 0 * 128 + 4 * kq);
            ulonglong2 h1 = *(const ulonglong2*)(hsp + 1 * 128 + 4 * kq);
            ulonglong2 h2 = *(const ulonglong2*)(hsp + 2 * 128 + 4 * kq);
            ulonglong2 h3 = *(const ulonglong2*)(hsp + 3 * 128 + 4 * kq);
            fma2(a0, h0.x, w0); fma2(a0, h0.y, w1);
            fma2(a1, h1.x, w0); fma2(a1, h1.y, w1);
            fma2(a2, h2.x, w0); fma2(a2, h2.y, w1);
            fma2(a3, h3.x, w0); fma2(a3, h3.y, w1);
            fma2(a4, h0.x, wv.x); fma2(a4, h0.y, wv.y);
            fma2(a5, h1.x, wv.x); fma2(a5, h1.y, wv.y);
            fma2(a6, h2.x, wv.x); fma2(a6, h2.y, wv.y);
            fma2(a7, h3.x, wv.x); fma2(a7, h3.y, wv.y);
        }
        float2 f0 = unpack2(a0), f1 = unpack2(a1), f2 = unpack2(a2), f3 = unpack2(a3);
        float2 f4 = unpack2(a4), f5 = unpack2(a5), f6 = unpack2(a6), f7 = unpack2(a7);
        float p0 = f0.x + f0.y, p1 = f1.x + f1.y, p2 = f2.x + f2.y, p3 = f3.x + f3.y;
        float q0 = f4.x + f4.y, q1 = f5.x + f5.y, q2 = f6.x + f6.y, q3 = f7.x + f7.y;

        if (ks == 1) {   // upper k-half: publish partials (g0, g1) per row
            *(float2*)&red[0 * 512 + 2 * jj] = make_float2(p0, q0);
            *(float2*)&red[1 * 512 + 2 * jj] = make_float2(p1, q1);
            *(float2*)&red[2 * 512 + 2 * jj] = make_float2(p2, q2);
            *(float2*)&red[3 * 512 + 2 * jj] = make_float2(p3, q3);
        }
        cpasync_wait1();       // xg[t] staged (group t done; only t+1 in flight)
        __syncthreads();       // bar1: red + xgs visible

        if (ks == 0) {         // combine + activation, write gact
            const float* xb = xgs + (t & 1) * 2048;
            float x00 = xb[g0 * 4 + 0], x01 = xb[g0 * 4 + 1],
                  x02 = xb[g0 * 4 + 2], x03 = xb[g0 * 4 + 3];
            float x10 = xb[(g0 + 1) * 4 + 0], x11 = xb[(g0 + 1) * 4 + 1],
                  x12 = xb[(g0 + 1) * 4 + 2], x13 = xb[(g0 + 1) * 4 + 3];
            float2 r0 = *(const float2*)&red[0 * 512 + 2 * jj];
            float2 r1 = *(const float2*)&red[1 * 512 + 2 * jj];
            float2 r2 = *(const float2*)&red[2 * 512 + 2 * jj];
            float2 r3 = *(const float2*)&red[3 * 512 + 2 * jj];
            float v00 = p0 + r0.x + x00, v10 = q0 + r0.y + x10;
            float v01 = p1 + r1.x + x01, v11 = q1 + r1.y + x11;
            float v02 = p2 + r2.x + x02, v12 = q2 + r2.y + x12;
            float v03 = p3 + r3.x + x03, v13 = q3 + r3.y + x13;
            if (gtype == 2) {
                v00 = tanhx(v00); v01 = tanhx(v01); v02 = tanhx(v02); v03 = tanhx(v03);
                v10 = tanhx(v10); v11 = tanhx(v11); v12 = tanhx(v12); v13 = tanhx(v13);
            } else {
                v00 = sigx(v00); v01 = sigx(v01); v02 = sigx(v02); v03 = sigx(v03);
                v10 = sigx(v10); v11 = sigx(v11); v12 = sigx(v12); v13 = sigx(v13);
            }
            *(float2*)&gact[0 * 512 + 2 * jj] = make_float2(v00, v10);
            *(float2*)&gact[1 * 512 + 2 * jj] = make_float2(v01, v11);
            *(float2*)&gact[2 * 512 + 2 * jj] = make_float2(v02, v12);
            *(float2*)&gact[3 * 512 + 2 * jj] = make_float2(v03, v13);
        }
        __syncthreads();       // bar2: gact complete

        // ---- phase 2: c/h update for (row bb, unit u) ----
        float iv = gact[bb * 512 + u];
        float fv = gact[bb * 512 + 128 + u];
        float gv = gact[bb * 512 + 256 + u];
        float ov = gact[bb * 512 + 384 + u];
        c = fv * c + iv * gv;
        float h = ov * tanhx(c);
        h_s[bb * 128 + u] = h;
        out[((size_t)(b0 + bb) * TSEQ + t) * HID + u] = h;
        if (t == TSEQ - 1)
            g_hN[layer * (NB * HID) + (b0 + bb) * HID + u] = h;
        __syncthreads();       // bar3: h_s ready for next step
    }
}

// =====================================================================
// Heads: hN [4,512,128] -> (opt, tp, sl, lot), each [4,512,4]
// =====================================================================
__global__ void heads_kernel(
    const float* __restrict__ Wopt, const float* __restrict__ bopt,
    const float* __restrict__ Wlot, const float* __restrict__ blot,
    const float* __restrict__ Wtp,  const float* __restrict__ btp,
    const float* __restrict__ Wsl,  const float* __restrict__ bsl,
    float* __restrict__ outp)
{
    int tid = blockIdx.x * blockDim.x + threadIdx.x;
    if (tid >= 4 * 2048) return;
    int head = tid >> 11;
    int r    = tid & 2047;
    const float* W; const float* b;
    if      (head == 0) { W = Wopt; b = bopt; }
    else if (head == 1) { W = Wtp;  b = btp;  }
    else if (head == 2) { W = Wsl;  b = bsl;  }
    else                { W = Wlot; b = blot; }

    float y0 = b[0], y1 = b[1], y2 = b[2], y3 = b[3];
    const float4* hv = (const float4*)&g_hN[r * HID];
    const float4* w0 = (const float4*)&W[0];
    const float4* w1 = (const float4*)&W[128];
    const float4* w2 = (const float4*)&W[256];
    const float4* w3 = (const float4*)&W[384];
#pragma unroll 8
    for (int q = 0; q < 32; q++) {
        float4 h = hv[q];
        float4 a  = w0[q]; y0 += h.x*a.x  + h.y*a.y  + h.z*a.z  + h.w*a.w;
        float4 bq = w1[q]; y1 += h.x*bq.x + h.y*bq.y + h.z*bq.z + h.w*bq.w;
        float4 cq = w2[q]; y2 += h.x*cq.x + h.y*cq.y + h.z*cq.z + h.w*cq.w;
        float4 dq = w3[q]; y3 += h.x*dq.x + h.y*dq.y + h.z*dq.z + h.w*dq.w;
    }
    float o0, o1, o2, o3;
    if (head == 0) {
        float m = fmaxf(fmaxf(y0, y1), fmaxf(y2, y3));
        float e0 = __expf(y0 - m), e1 = __expf(y1 - m),
              e2 = __expf(y2 - m), e3 = __expf(y3 - m);
        float s = e0 + e1 + e2 + e3;
        float p0 = e0 / s, p1 = e1 / s, p2 = e2 / s, p3 = e3 / s;
        m = fmaxf(fmaxf(p0, p1), fmaxf(p2, p3));
        e0 = __expf(p0 - m); e1 = __expf(p1 - m);
        e2 = __expf(p2 - m); e3 = __expf(p3 - m);
        s = e0 + e1 + e2 + e3;
        o0 = e0 / s; o1 = e1 / s; o2 = e2 / s; o3 = e3 / s;
    } else {
        o0 = sigx(sigx(y0)); o1 = sigx(sigx(y1));
        o2 = sigx(sigx(y2)); o3 = sigx(sigx(y3));
    }
    float* dst = outp + head * 8192 + r * 4;
    dst[0] = o0; dst[1] = o1; dst[2] = o2; dst[3] = o3;
}

// =====================================================================
extern "C" void kernel_launch(void* const* d_in, const int* in_sizes, int n_in,
                              void* d_out, int out_size)
{
    const float* x      = (const float*)d_in[0];
    const float* Wih0   = (const float*)d_in[1];
    const float* Whh0   = (const float*)d_in[2];
    const float* bih0   = (const float*)d_in[3];
    const float* bhh0   = (const float*)d_in[4];
    const float* Wih123 = (const float*)d_in[5];
    const float* Whh123 = (const float*)d_in[6];
    const float* bih123 = (const float*)d_in[7];
    const float* bhh123 = (const float*)d_in[8];
    const float* Wopt   = (const float*)d_in[9];
    const float* bopt   = (const float*)d_in[10];
    const float* Wlot   = (const float*)d_in[11];
    const float* blot   = (const float*)d_in[12];
    const float* Wtp    = (const float*)d_in[13];
    const float* btp    = (const float*)d_in[14];
    const float* Wsl    = (const float*)d_in[15];
    const float* bsl    = (const float*)d_in[16];
    float* outp = (float*)d_out;

    const int SM_PRE128 = 32 * 512 * 8 + 8 * 128 * 4;   // 135168
    const int SM_PRE32  = 8 * 32 * 4;                   // 1024
    const int SM_REC    = 131072 + (512 + 2048 + 2048 + 4096) * 4;  // 165888

    cudaFuncSetAttribute(precompute_kernel<128>,
                         cudaFuncAttributeMaxDynamicSharedMemorySize, SM_PRE128);
    cudaFuncSetAttribute(recurrent_kernel,
                         cudaFuncAttributeMaxDynamicSharedMemorySize, SM_REC);

    // layer 0
    precompute_kernel<32><<<148, 512, SM_PRE32>>>(x, 0, Wih0, bih0, bhh0);
    recurrent_kernel<<<128, 512, SM_REC>>>(Whh0, /*out=A*/0, /*layer*/0);
    // layer 1 (in A -> out B)
    precompute_kernel<128><<<148, 512, SM_PRE128>>>(nullptr, 0,
        Wih123 + 0 * G4 * HID, bih123 + 0 * G4, bhh123 + 0 * G4);
    recurrent_kernel<<<128, 512, SM_REC>>>(Whh123 + 0 * G4 * HID, 1, 1);
    // layer 2 (in B -> out A)
    precompute_kernel<128><<<148, 512, SM_PRE128>>>(nullptr, 1,
        Wih123 + 1 * G4 * HID, bih123 + 1 * G4, bhh123 + 1 * G4);
    recurrent_kernel<<<128, 512, SM_REC>>>(Whh123 + 1 * G4 * HID, 0, 2);
    // layer 3 (in A -> out B)
    precompute_kernel<128><<<148, 512, SM_PRE128>>>(nullptr, 0,
        Wih123 + 2 * G4 * HID, bih123 + 2 * G4, bhh123 + 2 * G4);
    recurrent_kernel<<<128, 512, SM_REC>>>(Whh123 + 2 * G4 * HID, 1, 3);
    // heads
    heads_kernel<<<(4 * 2048 + 255) / 256, 256>>>(
        Wopt, bopt, Wlot, blot, Wtp, btp, Wsl, bsl, outp);
}

// round 4
// speedup vs baseline: 1.1885x; 1.0806x over previous
#include <cuda_runtime.h>
#include <cstddef>

#define TSEQ 912
#define NB   512
#define HID  128
#define G4   512   // 4*H

typedef unsigned long long ull;

// ---------------- device scratch (static, allowed) ----------------
__device__ float g_xg[(size_t)TSEQ * G4 * NB];      // [t][gate][batch]
__device__ float g_bufA[(size_t)NB * TSEQ * HID];   // [b][t][u]
__device__ float g_bufB[(size_t)NB * TSEQ * HID];
__device__ float g_hN[4 * NB * HID];                // [layer][b][u]

// ---------------- f32x2 helpers ----------------
__device__ __forceinline__ ull pack2(float lo, float hi) {
    ull r;
    asm("mov.b64 %0, {%1, %2};" : "=l"(r)
        : "r"(__float_as_uint(lo)), "r"(__float_as_uint(hi)));
    return r;
}
__device__ __forceinline__ float2 unpack2(ull v) {
    unsigned lo, hi;
    asm("mov.b64 {%0, %1}, %2;" : "=r"(lo), "=r"(hi) : "l"(v));
    return make_float2(__uint_as_float(lo), __uint_as_float(hi));
}
__device__ __forceinline__ void fma2(ull& d, ull a, ull b) {
    asm("fma.rn.f32x2 %0, %1, %2, %0;" : "+l"(d) : "l"(a), "l"(b));
}

// ---------------- activations ----------------
__device__ __forceinline__ float sigx(float x) {
    x = fminf(fmaxf(x, -30.f), 30.f);
    return __fdividef(1.f, 1.f + __expf(-x));
}
__device__ __forceinline__ float tanhx(float x) {
    x = fminf(fmaxf(x, -15.f), 15.f);
    float e = __expf(2.f * x);
    return __fdividef(e - 1.f, e + 1.f);
}

// ---------------- cp.async helpers ----------------
__device__ __forceinline__ unsigned smem_u32(const void* p) {
    return (unsigned)__cvta_generic_to_shared(p);
}
__device__ __forceinline__ void cpasync16(unsigned saddr, const void* gaddr) {
    asm volatile("cp.async.ca.shared.global [%0], [%1], 16;"
                 :: "r"(saddr), "l"(gaddr));
}
__device__ __forceinline__ void cpasync_commit() {
    asm volatile("cp.async.commit_group;");
}
__device__ __forceinline__ void cpasync_wait0() {
    asm volatile("cp.async.wait_group 0;");
}
__device__ __forceinline__ void cpasync_wait1() {
    asm volatile("cp.async.wait_group 1;");
}

// =====================================================================
// Precompute: xg[t][g][b] = in[b][t][:] . Wih[g][:] + bih[g] + bhh[g]
// x tile double-buffered via cp.async; one barrier per tile.
// =====================================================================
template<int K>
__global__ __launch_bounds__(512, 1)
void precompute_kernel(const float* __restrict__ xext, int insel,
                       const float* __restrict__ Wih,
                       const float* __restrict__ bih,
                       const float* __restrict__ bhh)
{
    extern __shared__ float sm[];
    constexpr int KREG = (K < 64) ? K : 64;
    constexpr int KSM  = K - KREG;
    constexpr int CHUNKS = 8 * K / 4;           // 16B chunks per tile
    ull*   wsp = (ull*)sm;                      // [KSM/2][512]
    float* xt  = sm + (KSM / 2) * 512 * 2;      // [2][8][K]

    const int j = threadIdx.x;
    const float* in = (K == 32) ? xext : (insel ? g_bufB : g_bufA);

    ull wregp[KREG / 2];
#pragma unroll
    for (int kk = 0; kk < KREG / 2; kk++)
        wregp[kk] = pack2(Wih[j * K + 2 * kk], Wih[j * K + 2 * kk + 1]);
#pragma unroll
    for (int kk = 0; kk < KSM / 2; kk++)
        wsp[kk * 512 + j] = pack2(Wih[j * K + KREG + 2 * kk],
                                  Wih[j * K + KREG + 2 * kk + 1]);
    const float bsum = bih[j] + bhh[j];

    const unsigned xt_s = smem_u32(xt);
    const int NT = TSEQ * (NB / 8);
    const int stride = gridDim.x;

    // prologue: stage first tile into buffer 0
    int tile0 = blockIdx.x;
    if (tile0 < NT && j < CHUNKS) {
        int t  = tile0 >> 6;
        int b0 = (tile0 & 63) << 3;
        int r  = j / (K / 4), kk = j % (K / 4);
        cpasync16(xt_s + (unsigned)(r * K + kk * 4) * 4,
                  &in[((size_t)(b0 + r) * TSEQ + t) * K + kk * 4]);
    }
    cpasync_commit();

    int buf = 0;
    for (int tile = blockIdx.x; tile < NT; tile += stride) {
        cpasync_wait0();
        __syncthreads();

        // stage next tile into other buffer
        int nxt = tile + stride;
        if (nxt < NT && j < CHUNKS) {
            int tn  = nxt >> 6;
            int bn0 = (nxt & 63) << 3;
            int r   = j / (K / 4), kk = j % (K / 4);
            cpasync16(xt_s + (unsigned)((buf ^ 1) * 8 * K + r * K + kk * 4) * 4,
                      &in[((size_t)(bn0 + r) * TSEQ + tn) * K + kk * 4]);
        }
        cpasync_commit();

        const float* xtb = xt + buf * 8 * K;
        const int t  = tile >> 6;
        const int b0 = (tile & 63) << 3;

        ull acc[8] = {0, 0, 0, 0, 0, 0, 0, 0};
#pragma unroll
        for (int kq = 0; kq < KREG / 4; kq++) {
            ull w0 = wregp[2 * kq], w1 = wregp[2 * kq + 1];
#pragma unroll
            for (int r = 0; r < 8; r++) {
                ulonglong2 xv = *(const ulonglong2*)&xtb[r * K + 4 * kq];
                fma2(acc[r], xv.x, w0);
                fma2(acc[r], xv.y, w1);
            }
        }
        if (KSM > 0) {
#pragma unroll
            for (int kq = 0; kq < KSM / 4; kq++) {
                ull w0 = wsp[(2 * kq) * 512 + j];
                ull w1 = wsp[(2 * kq + 1) * 512 + j];
#pragma unroll
                for (int r = 0; r < 8; r++) {
                    ulonglong2 xv = *(const ulonglong2*)&xtb[r * K + KREG + 4 * kq];
                    fma2(acc[r], xv.x, w0);
                    fma2(acc[r], xv.y, w1);
                }
            }
        }
        float v[8];
#pragma unroll
        for (int r = 0; r < 8; r++) {
            float2 f = unpack2(acc[r]);
            v[r] = bsum + f.x + f.y;
        }
        float* dst = &g_xg[(size_t)(t * G4 + j) * NB + b0];
        *(float4*)(dst)     = make_float4(v[0], v[1], v[2], v[3]);
        *(float4*)(dst + 4) = make_float4(v[4], v[5], v[6], v[7]);
        buf ^= 1;
    }
}

// =====================================================================
// Recurrent kernel: one block per 4 batch rows, 912 steps, 2 barriers/step.
// Phase 1: thread j -> gates (2*(j&255), 2*(j&255)+1), k-half ks=j>>8.
//   Publishes partials for both gates to red[row][khalf][gate].
// Phase 2: thread j -> (row bb=j>>7, unit u=j&127): reduce 2 k-halves x
//   4 gates, add xg, activate, update c/h.
// xg staged into smem via cp.async double buffer.
// =====================================================================
__global__ __launch_bounds__(512, 1)
void recurrent_kernel(const float* __restrict__ Whh, int outsel, int layer)
{
    extern __shared__ char smraw[];
    ulonglong2* wsp2 = (ulonglong2*)smraw;                 // [16][512]  128 KB
    float* h_s  = (float*)(smraw + 131072);                // [4][128]     2 KB
    float* red  = h_s + 512;                               // [4][2][512] 16 KB
    float* xgs  = red + 4096;                              // [2][512][4] 16 KB

    const int j   = threadIdx.x;
    const int jj  = j & 255;
    const int ks  = j >> 8;          // k-half
    const int g0  = 2 * jj;
    const int b0  = blockIdx.x * 4;
    float* out = outsel ? g_bufB : g_bufA;

    // gate g0 weights (this k-half) -> registers, pre-paired
    ull wr[32];
#pragma unroll
    for (int kk = 0; kk < 32; kk++)
        wr[kk] = pack2(Whh[g0 * 128 + ks * 64 + 2 * kk],
                       Whh[g0 * 128 + ks * 64 + 2 * kk + 1]);
    // gate g1 weights (this k-half) -> smem, pre-paired, 16B granules
#pragma unroll
    for (int kq = 0; kq < 16; kq++) {
        ulonglong2 wv;
        wv.x = pack2(Whh[(g0 + 1) * 128 + ks * 64 + 4 * kq],
                     Whh[(g0 + 1) * 128 + ks * 64 + 4 * kq + 1]);
        wv.y = pack2(Whh[(g0 + 1) * 128 + ks * 64 + 4 * kq + 2],
                     Whh[(g0 + 1) * 128 + ks * 64 + 4 * kq + 3]);
        wsp2[kq * 512 + j] = wv;
    }
    h_s[j] = 0.f;

    const int u  = j & 127;
    const int bb = j >> 7;
    float c = 0.f;

    // prologue: stage xg[t=0] into buffer 0
    const unsigned xgs_s = smem_u32(xgs);
    cpasync16(xgs_s + (unsigned)j * 16, &g_xg[(size_t)j * NB + b0]);
    cpasync_commit();
    __syncthreads();

    const float* hsp = h_s + ks * 64;
    const ulonglong2* wbase = wsp2 + j;

    for (int t = 0; t < TSEQ; t++) {
        // prefetch xg[t+1] into the other buffer (phase2 of t-1 done => safe)
        {
            int tn = (t + 1 < TSEQ) ? (t + 1) : t;
            unsigned dst = xgs_s + (unsigned)(((t + 1) & 1) * 2048 + j * 4) * 4;
            cpasync16(dst, &g_xg[((size_t)tn * G4 + j) * NB + b0]);
            cpasync_commit();
        }

        // ---- phase 1: partial pre-activations (2 gates x 4 rows x 64 k) ----
        ull a0 = 0, a1 = 0, a2 = 0, a3 = 0;   // gate g0, rows 0..3
        ull a4 = 0, a5 = 0, a6 = 0, a7 = 0;   // gate g1, rows 0..3
#pragma unroll
        for (int kq = 0; kq < 16; kq++) {
            ulonglong2 wv = wbase[kq * 512];
            ull w0 = wr[2 * kq], w1 = wr[2 * kq + 1];
            ulonglong2 h0 = *(const ulonglong2*)(hsp + 0 * 128 + 4 * kq);
            ulonglong2 h1 = *(const ulonglong2*)(hsp + 1 * 128 + 4 * kq);
            ulonglong2 h2 = *(const ulonglong2*)(hsp + 2 * 128 + 4 * kq);
            ulonglong2 h3 = *(const ulonglong2*)(hsp + 3 * 128 + 4 * kq);
            fma2(a0, h0.x, w0); fma2(a0, h0.y, w1);
            fma2(a1, h1.x, w0); fma2(a1, h1.y, w1);
            fma2(a2, h2.x, w0); fma2(a2, h2.y, w1);
            fma2(a3, h3.x, w0); fma2(a3, h3.y, w1);
            fma2(a4, h0.x, wv.x); fma2(a4, h0.y, wv.y);
            fma2(a5, h1.x, wv.x); fma2(a5, h1.y, wv.y);
            fma2(a6, h2.x, wv.x); fma2(a6, h2.y, wv.y);
            fma2(a7, h3.x, wv.x); fma2(a7, h3.y, wv.y);
        }
        float2 f0 = unpack2(a0), f1 = unpack2(a1), f2 = unpack2(a2), f3 = unpack2(a3);
        float2 f4 = unpack2(a4), f5 = unpack2(a5), f6 = unpack2(a6), f7 = unpack2(a7);
        // publish partials: red[row][ks][gate], {g0, g1} as float2
        *(float2*)&red[0 * 1024 + ks * 512 + g0] = make_float2(f0.x + f0.y, f4.x + f4.y);
        *(float2*)&red[1 * 1024 + ks * 512 + g0] = make_float2(f1.x + f1.y, f5.x + f5.y);
        *(float2*)&red[2 * 1024 + ks * 512 + g0] = make_float2(f2.x + f2.y, f6.x + f6.y);
        *(float2*)&red[3 * 1024 + ks * 512 + g0] = make_float2(f3.x + f3.y, f7.x + f7.y);

        cpasync_wait1();       // xg[t] staged (only t+1 still in flight)
        __syncthreads();       // bar A: red + xgs visible

        // ---- phase 2: reduce + activate + c/h update for (row bb, unit u) ----
        {
            const float* rb = red + bb * 1024;
            const float* xb = xgs + (t & 1) * 2048;
            float pi = rb[u]       + rb[512 + u]       + xb[u * 4 + bb];
            float pf = rb[128 + u] + rb[512 + 128 + u] + xb[(128 + u) * 4 + bb];
            float pg = rb[256 + u] + rb[512 + 256 + u] + xb[(256 + u) * 4 + bb];
            float po = rb[384 + u] + rb[512 + 384 + u] + xb[(384 + u) * 4 + bb];
            float iv = sigx(pi);
            float fv = sigx(pf);
            float gv = tanhx(pg);
            float ov = sigx(po);
            c = fv * c + iv * gv;
            float h = ov * tanhx(c);
            h_s[bb * 128 + u] = h;
            out[((size_t)(b0 + bb) * TSEQ + t) * HID + u] = h;
            if (t == TSEQ - 1)
                g_hN[layer * (NB * HID) + (b0 + bb) * HID + u] = h;
        }
        __syncthreads();       // bar B: h_s ready for next step
    }
}

// =====================================================================
// Heads: hN [4,512,128] -> (opt, tp, sl, lot), each [4,512,4]
// =====================================================================
__global__ void heads_kernel(
    const float* __restrict__ Wopt, const float* __restrict__ bopt,
    const float* __restrict__ Wlot, const float* __restrict__ blot,
    const float* __restrict__ Wtp,  const float* __restrict__ btp,
    const float* __restrict__ Wsl,  const float* __restrict__ bsl,
    float* __restrict__ outp)
{
    int tid = blockIdx.x * blockDim.x + threadIdx.x;
    if (tid >= 4 * 2048) return;
    int head = tid >> 11;
    int r    = tid & 2047;
    const float* W; const float* b;
    if      (head == 0) { W = Wopt; b = bopt; }
    else if (head == 1) { W = Wtp;  b = btp;  }
    else if (head == 2) { W = Wsl;  b = bsl;  }
    else                { W = Wlot; b = blot; }

    float y0 = b[0], y1 = b[1], y2 = b[2], y3 = b[3];
    const float4* hv = (const float4*)&g_hN[r * HID];
    const float4* w0 = (const float4*)&W[0];
    const float4* w1 = (const float4*)&W[128];
    const float4* w2 = (const float4*)&W[256];
    const float4* w3 = (const float4*)&W[384];
#pragma unroll 8
    for (int q = 0; q < 32; q++) {
        float4 h = hv[q];
        float4 a  = w0[q]; y0 += h.x*a.x  + h.y*a.y  + h.z*a.z  + h.w*a.w;
        float4 bq = w1[q]; y1 += h.x*bq.x + h.y*bq.y + h.z*bq.z + h.w*bq.w;
        float4 cq = w2[q]; y2 += h.x*cq.x + h.y*cq.y + h.z*cq.z + h.w*cq.w;
        float4 dq = w3[q]; y3 += h.x*dq.x + h.y*dq.y + h.z*dq.z + h.w*dq.w;
    }
    float o0, o1, o2, o3;
    if (head == 0) {
        float m = fmaxf(fmaxf(y0, y1), fmaxf(y2, y3));
        float e0 = __expf(y0 - m), e1 = __expf(y1 - m),
              e2 = __expf(y2 - m), e3 = __expf(y3 - m);
        float s = e0 + e1 + e2 + e3;
        float p0 = e0 / s, p1 = e1 / s, p2 = e2 / s, p3 = e3 / s;
        m = fmaxf(fmaxf(p0, p1), fmaxf(p2, p3));
        e0 = __expf(p0 - m); e1 = __expf(p1 - m);
        e2 = __expf(p2 - m); e3 = __expf(p3 - m);
        s = e0 + e1 + e2 + e3;
        o0 = e0 / s; o1 = e1 / s; o2 = e2 / s; o3 = e3 / s;
    } else {
        o0 = sigx(sigx(y0)); o1 = sigx(sigx(y1));
        o2 = sigx(sigx(y2)); o3 = sigx(sigx(y3));
    }
    float* dst = outp + head * 8192 + r * 4;
    dst[0] = o0; dst[1] = o1; dst[2] = o2; dst[3] = o3;
}

// =====================================================================
extern "C" void kernel_launch(void* const* d_in, const int* in_sizes, int n_in,
                              void* d_out, int out_size)
{
    const float* x      = (const float*)d_in[0];
    const float* Wih0   = (const float*)d_in[1];
    const float* Whh0   = (const float*)d_in[2];
    const float* bih0   = (const float*)d_in[3];
    const float* bhh0   = (const float*)d_in[4];
    const float* Wih123 = (const float*)d_in[5];
    const float* Whh123 = (const float*)d_in[6];
    const float* bih123 = (const float*)d_in[7];
    const float* bhh123 = (const float*)d_in[8];
    const float* Wopt   = (const float*)d_in[9];
    const float* bopt   = (const float*)d_in[10];
    const float* Wlot   = (const float*)d_in[11];
    const float* blot   = (const float*)d_in[12];
    const float* Wtp    = (const float*)d_in[13];
    const float* btp    = (const float*)d_in[14];
    const float* Wsl    = (const float*)d_in[15];
    const float* bsl    = (const float*)d_in[16];
    float* outp = (float*)d_out;

    const int SM_PRE128 = 32 * 512 * 8 + 2 * 8 * 128 * 4;   // 139264
    const int SM_PRE32  = 2 * 8 * 32 * 4;                   // 2048
    const int SM_REC    = 131072 + (512 + 4096 + 4096) * 4; // 165888

    cudaFuncSetAttribute(precompute_kernel<128>,
                         cudaFuncAttributeMaxDynamicSharedMemorySize, SM_PRE128);
    cudaFuncSetAttribute(recurrent_kernel,
                         cudaFuncAttributeMaxDynamicSharedMemorySize, SM_REC);

    // layer 0
    precompute_kernel<32><<<148, 512, SM_PRE32>>>(x, 0, Wih0, bih0, bhh0);
    recurrent_kernel<<<128, 512, SM_REC>>>(Whh0, /*out=A*/0, /*layer*/0);
    // layer 1 (in A -> out B)
    precompute_kernel<128><<<148, 512, SM_PRE128>>>(nullptr, 0,
        Wih123 + 0 * G4 * HID, bih123 + 0 * G4, bhh123 + 0 * G4);
    recurrent_kernel<<<128, 512, SM_REC>>>(Whh123 + 0 * G4 * HID, 1, 1);
    // layer 2 (in B -> out A)
    precompute_kernel<128><<<148, 512, SM_PRE128>>>(nullptr, 1,
        Wih123 + 1 * G4 * HID, bih123 + 1 * G4, bhh123 + 1 * G4);
    recurrent_kernel<<<128, 512, SM_REC>>>(Whh123 + 1 * G4 * HID, 0, 2);
    // layer 3 (in A -> out B)
    precompute_kernel<128><<<148, 512, SM_PRE128>>>(nullptr, 0,
        Wih123 + 2 * G4 * HID, bih123 + 2 * G4, bhh123 + 2 * G4);
    recurrent_kernel<<<128, 512, SM_REC>>>(Whh123 + 2 * G4 * HID, 1, 3);
    // heads
    heads_kernel<<<(4 * 2048 + 255) / 256, 256>>>(
        Wopt, bopt, Wlot, blot, Wtp, btp, Wsl, bsl, outp);
}

// round 6
// speedup vs baseline: 1.9673x; 1.6553x over previous
#include <cuda_runtime.h>
#include <cuda_bf16.h>
#include <cstdint>
#include <cstddef>

#define TSEQ 912
#define NB   512
#define HID  128
#define G4   512   // 4*H

typedef unsigned long long ull;

// ---------------- device scratch (static, allowed) ----------------
__device__ float g_xg[(size_t)TSEQ * G4 * NB];      // [t][gate][batch]
__device__ float g_bufA[(size_t)NB * TSEQ * HID];   // [b][t][u]
__device__ float g_bufB[(size_t)NB * TSEQ * HID];
__device__ float g_hN[4 * NB * HID];                // [layer][b][u]

// ---------------- f32x2 helpers (layer-0 precompute) ----------------
__device__ __forceinline__ ull pack2(float lo, float hi) {
    ull r;
    asm("mov.b64 %0, {%1, %2};" : "=l"(r)
        : "r"(__float_as_uint(lo)), "r"(__float_as_uint(hi)));
    return r;
}
__device__ __forceinline__ float2 unpack2(ull v) {
    unsigned lo, hi;
    asm("mov.b64 {%0, %1}, %2;" : "=r"(lo), "=r"(hi) : "l"(v));
    return make_float2(__uint_as_float(lo), __uint_as_float(hi));
}
__device__ __forceinline__ void fma2(ull& d, ull a, ull b) {
    asm("fma.rn.f32x2 %0, %1, %2, %0;" : "+l"(d) : "l"(a), "l"(b));
}

// ---------------- activations ----------------
__device__ __forceinline__ float sigx(float x) {
    x = fminf(fmaxf(x, -30.f), 30.f);
    return __fdividef(1.f, 1.f + __expf(-x));
}
__device__ __forceinline__ float tanhx(float x) {
    x = fminf(fmaxf(x, -15.f), 15.f);
    float e = __expf(2.f * x);
    return __fdividef(e - 1.f, e + 1.f);
}

// ---------------- bf16 helpers ----------------
__device__ __forceinline__ float bf16_rn(float x) {
    return __bfloat162float(__float2bfloat16(x));
}
// packs {lo_half = a, hi_half = b}
__device__ __forceinline__ uint32_t pack_bf16x2(float a, float b) {
    uint32_t r;
    asm("cvt.rn.bf16x2.f32 %0, %1, %2;" : "=r"(r) : "f"(b), "f"(a));
    return r;
}

// ---------------- cp.async helpers (layer-0 precompute) ----------------
__device__ __forceinline__ unsigned smem_u32(const void* p) {
    return (unsigned)__cvta_generic_to_shared(p);
}
__device__ __forceinline__ void cpasync16(unsigned saddr, const void* gaddr) {
    asm volatile("cp.async.ca.shared.global [%0], [%1], 16;"
                 :: "r"(saddr), "l"(gaddr));
}
__device__ __forceinline__ void cpasync_commit() {
    asm volatile("cp.async.commit_group;");
}
__device__ __forceinline__ void cpasync_wait0() {
    asm volatile("cp.async.wait_group 0;");
}

// ---------------- warp mma m16n8k16 bf16 ----------------
__device__ __forceinline__ void mma16816(float* d, const uint32_t* a,
                                         const uint32_t* b) {
    asm volatile(
        "mma.sync.aligned.m16n8k16.row.col.f32.bf16.bf16.f32 "
        "{%0,%1,%2,%3}, {%4,%5,%6,%7}, {%8,%9}, {%0,%1,%2,%3};"
        : "+f"(d[0]), "+f"(d[1]), "+f"(d[2]), "+f"(d[3])
        : "r"(a[0]), "r"(a[1]), "r"(a[2]), "r"(a[3]), "r"(b[0]), "r"(b[1]));
}

// shared layout (both mma kernels):
//   alo    : 128 KB  Wlo fragments  [(w*2+mt)*8+kt][lane][16B]
//   bstage :   2 KB  B fragments as bf16 halves, word = kt*64 + lanepos*2 + reg
//   gact   : [4][520] fp32
#define MMA_ALO_BYTES   131072
#define MMA_BST_OFF     131072
#define MMA_GACT_OFF    (131072 + 2048)
#define MMA_SMEM        (MMA_GACT_OFF + 4 * 520 * 4)   // 141392

// convert fp32 weight matrix [512][128] -> Whi regs + Wlo smem fragments
__device__ __forceinline__ void convert_weights(
    const float* __restrict__ W, char* alo, int w, int gid, int qid, int l,
    uint32_t wa[2][8][4])
{
#pragma unroll
    for (int mt = 0; mt < 2; mt++) {
        const int gb = w * 32 + mt * 16;
#pragma unroll
        for (int kt = 0; kt < 8; kt++) {
            uint32_t lo4[4];
#pragma unroll
            for (int q = 0; q < 4; q++) {
                int row = gb + gid + (q & 1) * 8;
                int col = kt * 16 + qid * 2 + (q >> 1) * 8;
                float w0 = W[row * 128 + col];
                float w1 = W[row * 128 + col + 1];
                float h0 = bf16_rn(w0), h1 = bf16_rn(w1);
                wa[mt][kt][q] = pack_bf16x2(h0, h1);
                lo4[q] = pack_bf16x2(w0 - h0, w1 - h1);
            }
            *(uint4*)(alo + (((w * 2 + mt) * 8 + kt) * 32 + l) * 16) =
                make_uint4(lo4[0], lo4[1], lo4[2], lo4[3]);
        }
    }
}

// =====================================================================
// Layer-0 precompute (K=32, fp32 FFMA path — cheap)
// =====================================================================
template<int K>
__global__ __launch_bounds__(512, 1)
void precompute_kernel(const float* __restrict__ xext,
                       const float* __restrict__ Wih,
                       const float* __restrict__ bih,
                       const float* __restrict__ bhh)
{
    extern __shared__ float sm[];
    constexpr int CHUNKS = 8 * K / 4;
    float* xt = sm;                              // [2][8][K]

    const int j = threadIdx.x;
    const float* in = xext;

    ull wregp[K / 2];
#pragma unroll
    for (int kk = 0; kk < K / 2; kk++)
        wregp[kk] = pack2(Wih[j * K + 2 * kk], Wih[j * K + 2 * kk + 1]);
    const float bsum = bih[j] + bhh[j];

    const unsigned xt_s = smem_u32(xt);
    const int NT = TSEQ * (NB / 8);
    const int stride = gridDim.x;

    int tile0 = blockIdx.x;
    if (tile0 < NT && j < CHUNKS) {
        int t  = tile0 >> 6;
        int b0 = (tile0 & 63) << 3;
        int r  = j / (K / 4), kk = j % (K / 4);
        cpasync16(xt_s + (unsigned)(r * K + kk * 4) * 4,
                  &in[((size_t)(b0 + r) * TSEQ + t) * K + kk * 4]);
    }
    cpasync_commit();

    int buf = 0;
    for (int tile = blockIdx.x; tile < NT; tile += stride) {
        cpasync_wait0();
        __syncthreads();

        int nxt = tile + stride;
        if (nxt < NT && j < CHUNKS) {
            int tn  = nxt >> 6;
            int bn0 = (nxt & 63) << 3;
            int r   = j / (K / 4), kk = j % (K / 4);
            cpasync16(xt_s + (unsigned)((buf ^ 1) * 8 * K + r * K + kk * 4) * 4,
                      &in[((size_t)(bn0 + r) * TSEQ + tn) * K + kk * 4]);
        }
        cpasync_commit();

        const float* xtb = xt + buf * 8 * K;
        const int t  = tile >> 6;
        const int b0 = (tile & 63) << 3;

        ull acc[8] = {0, 0, 0, 0, 0, 0, 0, 0};
#pragma unroll
        for (int kq = 0; kq < K / 4; kq++) {
            ull w0 = wregp[2 * kq], w1 = wregp[2 * kq + 1];
#pragma unroll
            for (int r = 0; r < 8; r++) {
                ulonglong2 xv = *(const ulonglong2*)&xtb[r * K + 4 * kq];
                fma2(acc[r], xv.x, w0);
                fma2(acc[r], xv.y, w1);
            }
        }
        float v[8];
#pragma unroll
        for (int r = 0; r < 8; r++) {
            float2 f = unpack2(acc[r]);
            v[r] = bsum + f.x + f.y;
        }
        float* dst = &g_xg[(size_t)(t * G4 + j) * NB + b0];
        *(float4*)(dst)     = make_float4(v[0], v[1], v[2], v[3]);
        *(float4*)(dst + 4) = make_float4(v[4], v[5], v[6], v[7]);
        buf ^= 1;
    }
}

// =====================================================================
// MMA precompute (layers 1-3): xg[t][g][b0..3] = Wih . in[b][t][:] + bias
// B tile cols: [in_hi (4) | in_lo (4)]; D pairing via shfl_xor lane^2.
// =====================================================================
__global__ __launch_bounds__(512, 1)
void precompute_mma_kernel(const float* __restrict__ Wih, int insel,
                           const float* __restrict__ bih,
                           const float* __restrict__ bhh)
{
    extern __shared__ char smraw[];
    char*     alo    = smraw;
    uint32_t* bstage = (uint32_t*)(smraw + MMA_BST_OFF);
    float*    gact   = (float*)(smraw + MMA_GACT_OFF);

    const int j = threadIdx.x, w = j >> 5, l = j & 31;
    const int gid = l >> 2, qid = l & 3;
    const float* in = insel ? g_bufB : g_bufA;

    uint32_t wa[2][8][4];
    convert_weights(Wih, alo, w, gid, qid, l, wa);

    float bs[2][2];
#pragma unroll
    for (int mt = 0; mt < 2; mt++) {
        int g0 = w * 32 + mt * 16 + gid;
        bs[mt][0] = bih[g0] + bhh[g0];
        bs[mt][1] = bih[g0 + 8] + bhh[g0 + 8];
    }

    // conversion role: thread j -> (k = j&127, col = j>>7)
    const int ck = j & 127, ccol = j >> 7;
    const uint32_t word = (ck >> 4) * 64
                        + ((ccol * 4 + ((ck & 7) >> 1)) << 1) + ((ck >> 3) & 1);
    const uint32_t bhh_off = word * 4 + (ck & 1) * 2;
    const uint32_t bhl_off = bhh_off + 128;

    const int NT = TSEQ * (NB / 4);
    const int stride = gridDim.x;

    // prologue: stage tile0's input into bstage
    {
        int t = blockIdx.x >> 7, b0 = (blockIdx.x & 127) * 4;
        float xv = in[((size_t)(b0 + ccol) * TSEQ + t) * HID + ck];
        float hh = bf16_rn(xv);
        *(__nv_bfloat16*)((char*)bstage + bhh_off) = __float2bfloat16(hh);
        *(__nv_bfloat16*)((char*)bstage + bhl_off) = __float2bfloat16(xv - hh);
    }
    __syncthreads();

    for (int tile = blockIdx.x; tile < NT; tile += stride) {
        const int t  = tile >> 7;
        const int b0 = (tile & 127) * 4;

        float d[2][4];
#pragma unroll
        for (int mt = 0; mt < 2; mt++) {
            if (qid < 2) {
                d[mt][0] = bs[mt][0]; d[mt][1] = bs[mt][0];
                d[mt][2] = bs[mt][1]; d[mt][3] = bs[mt][1];
            } else {
                d[mt][0] = d[mt][1] = d[mt][2] = d[mt][3] = 0.f;
            }
        }

        // prefetch next tile's input value
        int nxt = tile + stride;
        float xnext = 0.f;
        if (nxt < NT) {
            int tn = nxt >> 7, bn = (nxt & 127) * 4;
            xnext = in[((size_t)(bn + ccol) * TSEQ + tn) * HID + ck];
        }

#pragma unroll
        for (int kt = 0; kt < 8; kt++) {
            uint2 bv = *(const uint2*)&bstage[kt * 64 + 2 * l];
            uint32_t bfr[2] = {bv.x, bv.y};
            uint4 av0 = *(const uint4*)(alo + (((w * 2 + 0) * 8 + kt) * 32 + l) * 16);
            uint4 av1 = *(const uint4*)(alo + (((w * 2 + 1) * 8 + kt) * 32 + l) * 16);
            mma16816(d[0], wa[0][kt], bfr);
            mma16816(d[1], wa[1][kt], bfr);
            mma16816(d[0], (const uint32_t*)&av0, bfr);
            mma16816(d[1], (const uint32_t*)&av1, bfr);
        }

#pragma unroll
        for (int mt = 0; mt < 2; mt++)
#pragma unroll
            for (int q = 0; q < 4; q++)
                d[mt][q] += __shfl_xor_sync(0xffffffffu, d[mt][q], 2);

        if (qid < 2) {
            int b = qid * 2;
#pragma unroll
            for (int mt = 0; mt < 2; mt++) {
                int g0 = w * 32 + mt * 16 + gid;
                gact[b * 520 + g0]           = d[mt][0];
                gact[(b + 1) * 520 + g0]     = d[mt][1];
                gact[b * 520 + g0 + 8]       = d[mt][2];
                gact[(b + 1) * 520 + g0 + 8] = d[mt][3];
            }
        }
        __syncthreads();   // gact ready; bstage reads complete

        // coalesced writeback + stage next tile's input
        {
            float4 o;
            o.x = gact[0 * 520 + j]; o.y = gact[1 * 520 + j];
            o.z = gact[2 * 520 + j]; o.w = gact[3 * 520 + j];
            *(float4*)&g_xg[((size_t)t * G4 + j) * NB + b0] = o;
            float nh = bf16_rn(xnext);
            *(__nv_bfloat16*)((char*)bstage + bhh_off) = __float2bfloat16(nh);
            *(__nv_bfloat16*)((char*)bstage + bhl_off) = __float2bfloat16(xnext - nh);
        }
        __syncthreads();   // bstage(next) complete
    }
}

// =====================================================================
// MMA recurrent: one block = 4 batch rows, 912 steps.
// Per step: D = Whi_regs·B + Wlo_smem·B, B cols = [h_hi(4) | h_lo(4)],
// accumulator init = xg (cols<4).  2 barriers/step.
// =====================================================================
__global__ __launch_bounds__(512, 1)
void recurrent_kernel(const float* __restrict__ Whh, int outsel, int layer)
{
    extern __shared__ char smraw[];
    char*     alo    = smraw;
    uint32_t* bstage = (uint32_t*)(smraw + MMA_BST_OFF);
    float*    gact   = (float*)(smraw + MMA_GACT_OFF);

    const int j = threadIdx.x, w = j >> 5, l = j & 31;
    const int gid = l >> 2, qid = l & 3;
    const int b0 = blockIdx.x * 4;
    float* out = outsel ? g_bufB : g_bufA;

    uint32_t wa[2][8][4];
    convert_weights(Whh, alo, w, gid, qid, l, wa);

    bstage[j] = 0;                 // h(0) = 0 (512 words)

    const int u  = j & 127;
    const int bb = j >> 7;
    const int gtype = w >> 2;      // 0:i 1:f 2:g 3:o (32 gates/warp within one type block)
    float c = 0.f;

    const uint32_t word = (u >> 4) * 64
                        + ((bb * 4 + ((u & 7) >> 1)) << 1) + ((u >> 3) & 1);
    const uint32_t bhh_off = word * 4 + (u & 1) * 2;
    const uint32_t bhl_off = bhh_off + 128;

    // prefetch xg[0]
    float2 xq[2][2];
    if (qid < 2) {
#pragma unroll
        for (int mt = 0; mt < 2; mt++) {
            int g0 = w * 32 + mt * 16 + gid;
            const float* p = &g_xg[(size_t)g0 * NB + b0 + qid * 2];
            xq[mt][0] = *(const float2*)p;
            xq[mt][1] = *(const float2*)(p + 8 * NB);
        }
    }
    __syncthreads();   // bstage zero + alo visible

    for (int t = 0; t < TSEQ; t++) {
        float d[2][4];
#pragma unroll
        for (int mt = 0; mt < 2; mt++) {
            if (qid < 2) {
                d[mt][0] = xq[mt][0].x; d[mt][1] = xq[mt][0].y;
                d[mt][2] = xq[mt][1].x; d[mt][3] = xq[mt][1].y;
            } else {
                d[mt][0] = d[mt][1] = d[mt][2] = d[mt][3] = 0.f;
            }
        }

        // prefetch xg[t+1]
        float2 xqn[2][2];
        {
            int tn = (t + 1 < TSEQ) ? (t + 1) : t;
            if (qid < 2) {
#pragma unroll
                for (int mt = 0; mt < 2; mt++) {
                    int g0 = w * 32 + mt * 16 + gid;
                    const float* p = &g_xg[((size_t)tn * G4 + g0) * NB + b0 + qid * 2];
                    xqn[mt][0] = *(const float2*)p;
                    xqn[mt][1] = *(const float2*)(p + 8 * NB);
                }
            }
        }

#pragma unroll
        for (int kt = 0; kt < 8; kt++) {
            uint2 bv = *(const uint2*)&bstage[kt * 64 + 2 * l];
            uint32_t bfr[2] = {bv.x, bv.y};
            uint4 av0 = *(const uint4*)(alo + (((w * 2 + 0) * 8 + kt) * 32 + l) * 16);
            uint4 av1 = *(const uint4*)(alo + (((w * 2 + 1) * 8 + kt) * 32 + l) * 16);
            mma16816(d[0], wa[0][kt], bfr);
            mma16816(d[1], wa[1][kt], bfr);
            mma16816(d[0], (const uint32_t*)&av0, bfr);
            mma16816(d[1], (const uint32_t*)&av1, bfr);
        }

#pragma unroll
        for (int mt = 0; mt < 2; mt++)
#pragma unroll
            for (int q = 0; q < 4; q++)
                d[mt][q] += __shfl_xor_sync(0xffffffffu, d[mt][q], 2);

        if (qid < 2) {
            int b = qid * 2;
#pragma unroll
            for (int mt = 0; mt < 2; mt++) {
                int g0 = w * 32 + mt * 16 + gid;
                float v0, v1, v2, v3;
                if (gtype == 2) {
                    v0 = tanhx(d[mt][0]); v1 = tanhx(d[mt][1]);
                    v2 = tanhx(d[mt][2]); v3 = tanhx(d[mt][3]);
                } else {
                    v0 = sigx(d[mt][0]); v1 = sigx(d[mt][1]);
                    v2 = sigx(d[mt][2]); v3 = sigx(d[mt][3]);
                }
                gact[b * 520 + g0]           = v0;
                gact[(b + 1) * 520 + g0]     = v1;
                gact[b * 520 + g0 + 8]       = v2;
                gact[(b + 1) * 520 + g0 + 8] = v3;
            }
        }
        __syncthreads();   // gact ready; bstage reads complete

        // phase 2: c/h update for (row bb, unit u)
        {
            float iv = gact[bb * 520 + u];
            float fv = gact[bb * 520 + 128 + u];
            float gv = gact[bb * 520 + 256 + u];
            float ov = gact[bb * 520 + 384 + u];
            c = fv * c + iv * gv;
            float h = ov * tanhx(c);
            out[((size_t)(b0 + bb) * TSEQ + t) * HID + u] = h;
            if (t == TSEQ - 1)
                g_hN[layer * (NB * HID) + (b0 + bb) * HID + u] = h;
            float hh = bf16_rn(h);
            *(__nv_bfloat16*)((char*)bstage + bhh_off) = __float2bfloat16(hh);
            *(__nv_bfloat16*)((char*)bstage + bhl_off) = __float2bfloat16(h - hh);
        }
        __syncthreads();   // bstage(t) complete for next step

#pragma unroll
        for (int mt = 0; mt < 2; mt++) {
            xq[mt][0] = xqn[mt][0];
            xq[mt][1] = xqn[mt][1];
        }
    }
}

// =====================================================================
// Heads: hN [4,512,128] -> (opt, tp, sl, lot), each [4,512,4]
// =====================================================================
__global__ void heads_kernel(
    const float* __restrict__ Wopt, const float* __restrict__ bopt,
    const float* __restrict__ Wlot, const float* __restrict__ blot,
    const float* __restrict__ Wtp,  const float* __restrict__ btp,
    const float* __restrict__ Wsl,  const float* __restrict__ bsl,
    float* __restrict__ outp)
{
    int tid = blockIdx.x * blockDim.x + threadIdx.x;
    if (tid >= 4 * 2048) return;
    int head = tid >> 11;
    int r    = tid & 2047;
    const float* W; const float* b;
    if      (head == 0) { W = Wopt; b = bopt; }
    else if (head == 1) { W = Wtp;  b = btp;  }
    else if (head == 2) { W = Wsl;  b = bsl;  }
    else                { W = Wlot; b = blot; }

    float y0 = b[0], y1 = b[1], y2 = b[2], y3 = b[3];
    const float4* hv = (const float4*)&g_hN[r * HID];
    const float4* w0 = (const float4*)&W[0];
    const float4* w1 = (const float4*)&W[128];
    const float4* w2 = (const float4*)&W[256];
    const float4* w3 = (const float4*)&W[384];
#pragma unroll 8
    for (int q = 0; q < 32; q++) {
        float4 h = hv[q];
        float4 a  = w0[q]; y0 += h.x*a.x  + h.y*a.y  + h.z*a.z  + h.w*a.w;
        float4 bq = w1[q]; y1 += h.x*bq.x + h.y*bq.y + h.z*bq.z + h.w*bq.w;
        float4 cq = w2[q]; y2 += h.x*cq.x + h.y*cq.y + h.z*cq.z + h.w*cq.w;
        float4 dq = w3[q]; y3 += h.x*dq.x + h.y*dq.y + h.z*dq.z + h.w*dq.w;
    }
    float o0, o1, o2, o3;
    if (head == 0) {
        float m = fmaxf(fmaxf(y0, y1), fmaxf(y2, y3));
        float e0 = __expf(y0 - m), e1 = __expf(y1 - m),
              e2 = __expf(y2 - m), e3 = __expf(y3 - m);
        float s = e0 + e1 + e2 + e3;
        float p0 = e0 / s, p1 = e1 / s, p2 = e2 / s, p3 = e3 / s;
        m = fmaxf(fmaxf(p0, p1), fmaxf(p2, p3));
        e0 = __expf(p0 - m); e1 = __expf(p1 - m);
        e2 = __expf(p2 - m); e3 = __expf(p3 - m);
        s = e0 + e1 + e2 + e3;
        o0 = e0 / s; o1 = e1 / s; o2 = e2 / s; o3 = e3 / s;
    } else {
        o0 = sigx(sigx(y0)); o1 = sigx(sigx(y1));
        o2 = sigx(sigx(y2)); o3 = sigx(sigx(y3));
    }
    float* dst = outp + head * 8192 + r * 4;
    dst[0] = o0; dst[1] = o1; dst[2] = o2; dst[3] = o3;
}

// =====================================================================
extern "C" void kernel_launch(void* const* d_in, const int* in_sizes, int n_in,
                              void* d_out, int out_size)
{
    const float* x      = (const float*)d_in[0];
    const float* Wih0   = (const float*)d_in[1];
    const float* Whh0   = (const float*)d_in[2];
    const float* bih0   = (const float*)d_in[3];
    const float* bhh0   = (const float*)d_in[4];
    const float* Wih123 = (const float*)d_in[5];
    const float* Whh123 = (const float*)d_in[6];
    const float* bih123 = (const float*)d_in[7];
    const float* bhh123 = (const float*)d_in[8];
    const float* Wopt   = (const float*)d_in[9];
    const float* bopt   = (const float*)d_in[10];
    const float* Wlot   = (const float*)d_in[11];
    const float* blot   = (const float*)d_in[12];
    const float* Wtp    = (const float*)d_in[13];
    const float* btp    = (const float*)d_in[14];
    const float* Wsl    = (const float*)d_in[15];
    const float* bsl    = (const float*)d_in[16];
    float* outp = (float*)d_out;

    const int SM_PRE32 = 2 * 8 * 32 * 4;   // 2048

    cudaFuncSetAttribute(recurrent_kernel,
                         cudaFuncAttributeMaxDynamicSharedMemorySize, MMA_SMEM);
    cudaFuncSetAttribute(precompute_mma_kernel,
                         cudaFuncAttributeMaxDynamicSharedMemorySize, MMA_SMEM);

    // layer 0
    precompute_kernel<32><<<148, 512, SM_PRE32>>>(x, Wih0, bih0, bhh0);
    recurrent_kernel<<<128, 512, MMA_SMEM>>>(Whh0, /*out=A*/0, /*layer*/0);
    // layer 1 (in A -> out B)
    precompute_mma_kernel<<<148, 512, MMA_SMEM>>>(Wih123 + 0 * G4 * HID, 0,
        bih123 + 0 * G4, bhh123 + 0 * G4);
    recurrent_kernel<<<128, 512, MMA_SMEM>>>(Whh123 + 0 * G4 * HID, 1, 1);
    // layer 2 (in B -> out A)
    precompute_mma_kernel<<<148, 512, MMA_SMEM>>>(Wih123 + 1 * G4 * HID, 1,
        bih123 + 1 * G4, bhh123 + 1 * G4);
    recurrent_kernel<<<128, 512, MMA_SMEM>>>(Whh123 + 1 * G4 * HID, 0, 2);
    // layer 3 (in A -> out B)
    precompute_mma_kernel<<<148, 512, MMA_SMEM>>>(Wih123 + 2 * G4 * HID, 0,
        bih123 + 2 * G4, bhh123 + 2 * G4);
    recurrent_kernel<<<128, 512, MMA_SMEM>>>(Whh123 + 2 * G4 * HID, 1, 3);
    // heads
    heads_kernel<<<(4 * 2048 + 255) / 256, 256>>>(
        Wopt, bopt, Wlot, blot, Wtp, btp, Wsl, bsl, outp);
}

// round 7
// speedup vs baseline: 2.4798x; 1.2605x over previous
#include <cuda_runtime.h>
#include <cuda_bf16.h>
#include <cstdint>
#include <cstddef>

#define TSEQ 912
#define NB   512
#define HID  128
#define G4   512   // 4*H

typedef unsigned long long ull;

// ---------------- device scratch (static, allowed) ----------------
// layout: [t][bgrp (NB/4)][gate (512)][4 batch]
__device__ float g_xg[(size_t)TSEQ * (NB / 4) * G4 * 4];
__device__ float g_bufA[(size_t)NB * TSEQ * HID];   // [b][t][u]
__device__ float g_bufB[(size_t)NB * TSEQ * HID];
__device__ float g_hN[4 * NB * HID];                // [layer][b][u]

// ---------------- f32x2 helpers (layer-0 precompute) ----------------
__device__ __forceinline__ ull pack2(float lo, float hi) {
    ull r;
    asm("mov.b64 %0, {%1, %2};" : "=l"(r)
        : "r"(__float_as_uint(lo)), "r"(__float_as_uint(hi)));
    return r;
}
__device__ __forceinline__ float2 unpack2(ull v) {
    unsigned lo, hi;
    asm("mov.b64 {%0, %1}, %2;" : "=r"(lo), "=r"(hi) : "l"(v));
    return make_float2(__uint_as_float(lo), __uint_as_float(hi));
}
__device__ __forceinline__ void fma2(ull& d, ull a, ull b) {
    asm("fma.rn.f32x2 %0, %1, %2, %0;" : "+l"(d) : "l"(a), "l"(b));
}

// ---------------- activations ----------------
__device__ __forceinline__ float sigx(float x) {
    x = fminf(fmaxf(x, -30.f), 30.f);
    return __fdividef(1.f, 1.f + __expf(-x));
}
__device__ __forceinline__ float tanhx(float x) {
    x = fminf(fmaxf(x, -15.f), 15.f);
    float e = __expf(2.f * x);
    return __fdividef(e - 1.f, e + 1.f);
}

// ---------------- bf16 helpers ----------------
__device__ __forceinline__ float bf16_rn(float x) {
    return __bfloat162float(__float2bfloat16(x));
}
__device__ __forceinline__ uint32_t pack_bf16x2(float a, float b) {
    uint32_t r;
    asm("cvt.rn.bf16x2.f32 %0, %1, %2;" : "=r"(r) : "f"(b), "f"(a));
    return r;
}

// ---------------- cp.async helpers (layer-0 precompute) ----------------
__device__ __forceinline__ unsigned smem_u32(const void* p) {
    return (unsigned)__cvta_generic_to_shared(p);
}
__device__ __forceinline__ void cpasync16(unsigned saddr, const void* gaddr) {
    asm volatile("cp.async.ca.shared.global [%0], [%1], 16;"
                 :: "r"(saddr), "l"(gaddr));
}
__device__ __forceinline__ void cpasync_commit() {
    asm volatile("cp.async.commit_group;");
}
__device__ __forceinline__ void cpasync_wait0() {
    asm volatile("cp.async.wait_group 0;");
}

// ---------------- warp mma m16n8k16 bf16 ----------------
__device__ __forceinline__ void mma16816(float* d, const uint32_t* a,
                                         const uint32_t* b) {
    asm volatile(
        "mma.sync.aligned.m16n8k16.row.col.f32.bf16.bf16.f32 "
        "{%0,%1,%2,%3}, {%4,%5,%6,%7}, {%8,%9}, {%0,%1,%2,%3};"
        : "+f"(d[0]), "+f"(d[1]), "+f"(d[2]), "+f"(d[3])
        : "r"(a[0]), "r"(a[1]), "r"(a[2]), "r"(a[3]), "r"(b[0]), "r"(b[1]));
}

// shared layouts:
#define ALO_BYTES    131072
#define REC_BST_OFF  131072                    // 2 buffers x 512 words
#define REC_SMEM     (131072 + 4096)
#define PRE_BST_OFF  131072                    // 1 buffer x 512 words
#define PRE_GACT_OFF (131072 + 2048)
#define PRE_SMEM     (PRE_GACT_OFF + 4 * 520 * 4)

// convert fp32 weights [512][128] -> Whi regs + Wlo smem fragments.
// REORDER=true: warp w's A rows map to gate (rowfrag>>2)*128 + w*8 + mt*4 + (rowfrag&3)
// REORDER=false: gate = w*32 + mt*16 + rowfrag
template<bool REORDER>
__device__ __forceinline__ void convert_weights(
    const float* __restrict__ W, char* alo, int w, int gid, int qid, int l,
    uint32_t wa[2][8][4])
{
#pragma unroll
    for (int mt = 0; mt < 2; mt++) {
#pragma unroll
        for (int kt = 0; kt < 8; kt++) {
            uint32_t lo4[4];
#pragma unroll
            for (int q = 0; q < 4; q++) {
                int rf = gid + (q & 1) * 8;
                int row;
                if (REORDER)
                    row = (rf >> 2) * 128 + w * 8 + mt * 4 + (rf & 3);
                else
                    row = w * 32 + mt * 16 + rf;
                int col = kt * 16 + qid * 2 + (q >> 1) * 8;
                float w0 = W[row * 128 + col];
                float w1 = W[row * 128 + col + 1];
                float h0 = bf16_rn(w0), h1 = bf16_rn(w1);
                wa[mt][kt][q] = pack_bf16x2(h0, h1);
                lo4[q] = pack_bf16x2(w0 - h0, w1 - h1);
            }
            *(uint4*)(alo + (((w * 2 + mt) * 8 + kt) * 32 + l) * 16) =
                make_uint4(lo4[0], lo4[1], lo4[2], lo4[3]);
        }
    }
}

// =====================================================================
// Layer-0 precompute (K=32, fp32 FFMA path)
// =====================================================================
template<int K>
__global__ __launch_bounds__(512, 1)
void precompute_kernel(const float* __restrict__ xext,
                       const float* __restrict__ Wih,
                       const float* __restrict__ bih,
                       const float* __restrict__ bhh)
{
    extern __shared__ float sm[];
    constexpr int CHUNKS = 8 * K / 4;
    float* xt = sm;                              // [2][8][K]

    const int j = threadIdx.x;
    const float* in = xext;

    ull wregp[K / 2];
#pragma unroll
    for (int kk = 0; kk < K / 2; kk++)
        wregp[kk] = pack2(Wih[j * K + 2 * kk], Wih[j * K + 2 * kk + 1]);
    const float bsum = bih[j] + bhh[j];

    const unsigned xt_s = smem_u32(xt);
    const int NT = TSEQ * (NB / 8);
    const int stride = gridDim.x;

    int tile0 = blockIdx.x;
    if (tile0 < NT && j < CHUNKS) {
        int t  = tile0 >> 6;
        int b0 = (tile0 & 63) << 3;
        int r  = j / (K / 4), kk = j % (K / 4);
        cpasync16(xt_s + (unsigned)(r * K + kk * 4) * 4,
                  &in[((size_t)(b0 + r) * TSEQ + t) * K + kk * 4]);
    }
    cpasync_commit();

    int buf = 0;
    for (int tile = blockIdx.x; tile < NT; tile += stride) {
        cpasync_wait0();
        __syncthreads();

        int nxt = tile + stride;
        if (nxt < NT && j < CHUNKS) {
            int tn  = nxt >> 6;
            int bn0 = (nxt & 63) << 3;
            int r   = j / (K / 4), kk = j % (K / 4);
            cpasync16(xt_s + (unsigned)((buf ^ 1) * 8 * K + r * K + kk * 4) * 4,
                      &in[((size_t)(bn0 + r) * TSEQ + tn) * K + kk * 4]);
        }
        cpasync_commit();

        const float* xtb = xt + buf * 8 * K;
        const int t  = tile >> 6;
        const int b0 = (tile & 63) << 3;

        ull acc[8] = {0, 0, 0, 0, 0, 0, 0, 0};
#pragma unroll
        for (int kq = 0; kq < K / 4; kq++) {
            ull w0 = wregp[2 * kq], w1 = wregp[2 * kq + 1];
#pragma unroll
            for (int r = 0; r < 8; r++) {
                ulonglong2 xv = *(const ulonglong2*)&xtb[r * K + 4 * kq];
                fma2(acc[r], xv.x, w0);
                fma2(acc[r], xv.y, w1);
            }
        }
        float v[8];
#pragma unroll
        for (int r = 0; r < 8; r++) {
            float2 f = unpack2(acc[r]);
            v[r] = bsum + f.x + f.y;
        }
        // new layout: [t][bgrp][gate][4]
        float* d1 = &g_xg[(((size_t)t * 128 + (b0 >> 2)) * 512 + j) * 4];
        *(float4*)d1          = make_float4(v[0], v[1], v[2], v[3]);
        *(float4*)(d1 + 2048) = make_float4(v[4], v[5], v[6], v[7]);
        buf ^= 1;
    }
}

// =====================================================================
// MMA precompute (layers 1-3): xg[t][bgrp][g][0..3] = Wih . in + bias
// =====================================================================
__global__ __launch_bounds__(512, 1)
void precompute_mma_kernel(const float* __restrict__ Wih, int insel,
                           const float* __restrict__ bih,
                           const float* __restrict__ bhh)
{
    extern __shared__ char smraw[];
    char*     alo    = smraw;
    uint32_t* bstage = (uint32_t*)(smraw + PRE_BST_OFF);
    float*    gact   = (float*)(smraw + PRE_GACT_OFF);

    const int j = threadIdx.x, w = j >> 5, l = j & 31;
    const int gid = l >> 2, qid = l & 3;
    const float* in = insel ? g_bufB : g_bufA;

    uint32_t wa[2][8][4];
    convert_weights<false>(Wih, alo, w, gid, qid, l, wa);

    float bs[2][2];
#pragma unroll
    for (int mt = 0; mt < 2; mt++) {
        int g0 = w * 32 + mt * 16 + gid;
        bs[mt][0] = bih[g0] + bhh[g0];
        bs[mt][1] = bih[g0 + 8] + bhh[g0 + 8];
    }

    // conversion role: thread j -> (k = j&127, col = j>>7)
    const int ck = j & 127, ccol = j >> 7;
    const uint32_t word = (ck >> 4) * 64
                        + ((ccol * 4 + ((ck & 7) >> 1)) << 1) + ((ck >> 3) & 1);
    const uint32_t bhh_off = word * 4 + (ck & 1) * 2;
    const uint32_t bhl_off = bhh_off + 128;

    const int NT = TSEQ * (NB / 4);
    const int stride = gridDim.x;

    {
        int t = blockIdx.x >> 7, b0 = (blockIdx.x & 127) * 4;
        float xv = in[((size_t)(b0 + ccol) * TSEQ + t) * HID + ck];
        float hh = bf16_rn(xv);
        *(__nv_bfloat16*)((char*)bstage + bhh_off) = __float2bfloat16(hh);
        *(__nv_bfloat16*)((char*)bstage + bhl_off) = __float2bfloat16(xv - hh);
    }
    __syncthreads();

    for (int tile = blockIdx.x; tile < NT; tile += stride) {
        const int t  = tile >> 7;
        const int b0 = (tile & 127) * 4;

        float d[2][4];
#pragma unroll
        for (int mt = 0; mt < 2; mt++) {
            if (qid < 2) {
                d[mt][0] = bs[mt][0]; d[mt][1] = bs[mt][0];
                d[mt][2] = bs[mt][1]; d[mt][3] = bs[mt][1];
            } else {
                d[mt][0] = d[mt][1] = d[mt][2] = d[mt][3] = 0.f;
            }
        }

        int nxt = tile + stride;
        float xnext = 0.f;
        if (nxt < NT) {
            int tn = nxt >> 7, bn = (nxt & 127) * 4;
            xnext = in[((size_t)(bn + ccol) * TSEQ + tn) * HID + ck];
        }

#pragma unroll
        for (int kt = 0; kt < 8; kt++) {
            uint2 bv = *(const uint2*)&bstage[kt * 64 + 2 * l];
            uint32_t bfr[2] = {bv.x, bv.y};
            uint4 av0 = *(const uint4*)(alo + (((w * 2 + 0) * 8 + kt) * 32 + l) * 16);
            uint4 av1 = *(const uint4*)(alo + (((w * 2 + 1) * 8 + kt) * 32 + l) * 16);
            mma16816(d[0], wa[0][kt], bfr);
            mma16816(d[1], wa[1][kt], bfr);
            mma16816(d[0], (const uint32_t*)&av0, bfr);
            mma16816(d[1], (const uint32_t*)&av1, bfr);
        }

#pragma unroll
        for (int mt = 0; mt < 2; mt++)
#pragma unroll
            for (int q = 0; q < 4; q++)
                d[mt][q] += __shfl_xor_sync(0xffffffffu, d[mt][q], 2);

        if (qid < 2) {
            int b = qid * 2;
#pragma unroll
            for (int mt = 0; mt < 2; mt++) {
                int g0 = w * 32 + mt * 16 + gid;
                gact[b * 520 + g0]           = d[mt][0];
                gact[(b + 1) * 520 + g0]     = d[mt][1];
                gact[b * 520 + g0 + 8]       = d[mt][2];
                gact[(b + 1) * 520 + g0 + 8] = d[mt][3];
            }
        }
        __syncthreads();

        {
            float4 o;
            o.x = gact[0 * 520 + j]; o.y = gact[1 * 520 + j];
            o.z = gact[2 * 520 + j]; o.w = gact[3 * 520 + j];
            // coalesced: [t][bgrp][gate j][4]
            *(float4*)&g_xg[(((size_t)t * 128 + (b0 >> 2)) * 512 + j) * 4] = o;
            float nh = bf16_rn(xnext);
            *(__nv_bfloat16*)((char*)bstage + bhh_off) = __float2bfloat16(nh);
            *(__nv_bfloat16*)((char*)bstage + bhl_off) = __float2bfloat16(xnext - nh);
        }
        __syncthreads();
    }
}

// =====================================================================
// MMA recurrent v2: reordered gate rows, register c/h update,
// double-buffered B stage, ONE barrier per step.
// Warp w owns units [w*8, w*8+8) x all 4 gate types.
// =====================================================================
__global__ __launch_bounds__(512, 1)
void recurrent_kernel(const float* __restrict__ Whh, int outsel, int layer)
{
    extern __shared__ char smraw[];
    char*     alo    = smraw;
    uint32_t* bstage = (uint32_t*)(smraw + REC_BST_OFF);   // [2][512] words

    const int j = threadIdx.x, w = j >> 5, l = j & 31;
    const int gid = l >> 2, qid = l & 3;
    const int bgrp = blockIdx.x;
    const int b0 = bgrp * 4;
    float* out = outsel ? g_bufB : g_bufA;

    uint32_t wa[2][8][4];
    convert_weights<true>(Whh, alo, w, gid, qid, l, wa);

    bstage[j] = 0;            // both buffers zero (h(0) = 0)
    bstage[j + 512] = 0;

    // cell roles (qid < 2 lanes produce 2 cells, one per mt)
    const int cb  = 2 * qid + (gid >> 2);      // batch col 0..3
    const int ulo = gid & 3;
    float c0 = 0.f, c1 = 0.f;

    // xg gate indices: row gid -> gate glo, row gid+8 -> glo + 256
    // glo(mt) = (gid>>2)*128 + w*8 + mt*4 + ulo
    const int glo0 = (gid >> 2) * 128 + w * 8 + 0 * 4 + ulo;
    const int glo1 = glo0 + 4;

    // bstage write offsets per mt: unit u = w*8 + mt*4 + ulo, col cb
    uint32_t bsh[2], bsl_[2];
#pragma unroll
    for (int mt = 0; mt < 2; mt++) {
        int u = w * 8 + mt * 4 + ulo;
        uint32_t word = (u >> 4) * 64 + ((cb * 4 + ((u & 7) >> 1)) << 1) + ((u >> 3) & 1);
        bsh[mt] = word * 4 + (u & 1) * 2;
        bsl_[mt] = bsh[mt] + 128;
    }

    // prefetch xg[0]
    float2 xq[2][2];
    if (qid < 2) {
        const float* p0 = &g_xg[((size_t)0 + bgrp) * 2048 + glo0 * 4 + 2 * qid];
        xq[0][0] = *(const float2*)p0;
        xq[0][1] = *(const float2*)(p0 + 1024);
        const float* p1 = &g_xg[((size_t)0 + bgrp) * 2048 + glo1 * 4 + 2 * qid];
        xq[1][0] = *(const float2*)p1;
        xq[1][1] = *(const float2*)(p1 + 1024);
    }
    __syncthreads();   // bstage zero + alo visible

    for (int t = 0; t < TSEQ; t++) {
        float d[2][4];
#pragma unroll
        for (int mt = 0; mt < 2; mt++) {
            if (qid < 2) {
                d[mt][0] = xq[mt][0].x; d[mt][1] = xq[mt][0].y;
                d[mt][2] = xq[mt][1].x; d[mt][3] = xq[mt][1].y;
            } else {
                d[mt][0] = d[mt][1] = d[mt][2] = d[mt][3] = 0.f;
            }
        }

        // prefetch xg[t+1]
        {
            int tn = (t + 1 < TSEQ) ? (t + 1) : t;
            if (qid < 2) {
                const float* p0 = &g_xg[((size_t)tn * 128 + bgrp) * 2048 + glo0 * 4 + 2 * qid];
                xq[0][0] = *(const float2*)p0;
                xq[0][1] = *(const float2*)(p0 + 1024);
                const float* p1 = &g_xg[((size_t)tn * 128 + bgrp) * 2048 + glo1 * 4 + 2 * qid];
                xq[1][0] = *(const float2*)p1;
                xq[1][1] = *(const float2*)(p1 + 1024);
            }
        }

        const uint32_t* bcur = bstage + (t & 1) * 512;
#pragma unroll
        for (int kt = 0; kt < 8; kt++) {
            uint2 bv = *(const uint2*)&bcur[kt * 64 + 2 * l];
            uint32_t bfr[2] = {bv.x, bv.y};
            uint4 av0 = *(const uint4*)(alo + (((w * 2 + 0) * 8 + kt) * 32 + l) * 16);
            uint4 av1 = *(const uint4*)(alo + (((w * 2 + 1) * 8 + kt) * 32 + l) * 16);
            mma16816(d[0], wa[0][kt], bfr);
            mma16816(d[1], wa[1][kt], bfr);
            mma16816(d[0], (const uint32_t*)&av0, bfr);
            mma16816(d[1], (const uint32_t*)&av1, bfr);
        }

        // pair hi/lo columns
#pragma unroll
        for (int mt = 0; mt < 2; mt++)
#pragma unroll
            for (int q = 0; q < 4; q++)
                d[mt][q] += __shfl_xor_sync(0xffffffffu, d[mt][q], 2);

        // exchange gate types across gid^4 (lane^16)
        float e[2][4];
#pragma unroll
        for (int mt = 0; mt < 2; mt++)
#pragma unroll
            for (int q = 0; q < 4; q++)
                e[mt][q] = __shfl_xor_sync(0xffffffffu, d[mt][q], 16);

        char* bnx = (char*)bstage + ((t + 1) & 1) * 2048;
        if (qid < 2) {
#pragma unroll
            for (int mt = 0; mt < 2; mt++) {
                float pi, pf, pg, po;
                if (gid < 4) { pi = d[mt][0]; pf = e[mt][0]; pg = d[mt][2]; po = e[mt][2]; }
                else         { pi = e[mt][1]; pf = d[mt][1]; pg = e[mt][3]; po = d[mt][3]; }
                float iv = sigx(pi), fv = sigx(pf), gv = tanhx(pg), ov = sigx(po);
                float& c = mt ? c1 : c0;
                c = fv * c + iv * gv;
                float h = ov * tanhx(c);
                int u = w * 8 + mt * 4 + ulo;
                out[((size_t)(b0 + cb) * TSEQ + t) * HID + u] = h;
                if (t == TSEQ - 1)
                    g_hN[layer * (NB * HID) + (b0 + cb) * HID + u] = h;
                float hh = bf16_rn(h);
                *(__nv_bfloat16*)(bnx + bsh[mt]) = __float2bfloat16(hh);
                *(__nv_bfloat16*)(bnx + bsl_[mt]) = __float2bfloat16(h - hh);
            }
        }
        __syncthreads();   // h(t) published for step t+1
    }
}

// =====================================================================
// Heads: hN [4,512,128] -> (opt, tp, sl, lot), each [4,512,4]
// =====================================================================
__global__ void heads_kernel(
    const float* __restrict__ Wopt, const float* __restrict__ bopt,
    const float* __restrict__ Wlot, const float* __restrict__ blot,
    const float* __restrict__ Wtp,  const float* __restrict__ btp,
    const float* __restrict__ Wsl,  const float* __restrict__ bsl,
    float* __restrict__ outp)
{
    int tid = blockIdx.x * blockDim.x + threadIdx.x;
    if (tid >= 4 * 2048) return;
    int head = tid >> 11;
    int r    = tid & 2047;
    const float* W; const float* b;
    if      (head == 0) { W = Wopt; b = bopt; }
    else if (head == 1) { W = Wtp;  b = btp;  }
    else if (head == 2) { W = Wsl;  b = bsl;  }
    else                { W = Wlot; b = blot; }

    float y0 = b[0], y1 = b[1], y2 = b[2], y3 = b[3];
    const float4* hv = (const float4*)&g_hN[r * HID];
    const float4* w0 = (const float4*)&W[0];
    const float4* w1 = (const float4*)&W[128];
    const float4* w2 = (const float4*)&W[256];
    const float4* w3 = (const float4*)&W[384];
#pragma unroll 8
    for (int q = 0; q < 32; q++) {
        float4 h = hv[q];
        float4 a  = w0[q]; y0 += h.x*a.x  + h.y*a.y  + h.z*a.z  + h.w*a.w;
        float4 bq = w1[q]; y1 += h.x*bq.x + h.y*bq.y + h.z*bq.z + h.w*bq.w;
        float4 cq = w2[q]; y2 += h.x*cq.x + h.y*cq.y + h.z*cq.z + h.w*cq.w;
        float4 dq = w3[q]; y3 += h.x*dq.x + h.y*dq.y + h.z*dq.z + h.w*dq.w;
    }
    float o0, o1, o2, o3;
    if (head == 0) {
        float m = fmaxf(fmaxf(y0, y1), fmaxf(y2, y3));
        float e0 = __expf(y0 - m), e1 = __expf(y1 - m),
              e2 = __expf(y2 - m), e3 = __expf(y3 - m);
        float s = e0 + e1 + e2 + e3;
        float p0 = e0 / s, p1 = e1 / s, p2 = e2 / s, p3 = e3 / s;
        m = fmaxf(fmaxf(p0, p1), fmaxf(p2, p3));
        e0 = __expf(p0 - m); e1 = __expf(p1 - m);
        e2 = __expf(p2 - m); e3 = __expf(p3 - m);
        s = e0 + e1 + e2 + e3;
        o0 = e0 / s; o1 = e1 / s; o2 = e2 / s; o3 = e3 / s;
    } else {
        o0 = sigx(sigx(y0)); o1 = sigx(sigx(y1));
        o2 = sigx(sigx(y2)); o3 = sigx(sigx(y3));
    }
    float* dst = outp + head * 8192 + r * 4;
    dst[0] = o0; dst[1] = o1; dst[2] = o2; dst[3] = o3;
}

// =====================================================================
extern "C" void kernel_launch(void* const* d_in, const int* in_sizes, int n_in,
                              void* d_out, int out_size)
{
    const float* x      = (const float*)d_in[0];
    const float* Wih0   = (const float*)d_in[1];
    const float* Whh0   = (const float*)d_in[2];
    const float* bih0   = (const float*)d_in[3];
    const float* bhh0   = (const float*)d_in[4];
    const float* Wih123 = (const float*)d_in[5];
    const float* Whh123 = (const float*)d_in[6];
    const float* bih123 = (const float*)d_in[7];
    const float* bhh123 = (const float*)d_in[8];
    const float* Wopt   = (const float*)d_in[9];
    const float* bopt   = (const float*)d_in[10];
    const float* Wlot   = (const float*)d_in[11];
    const float* blot   = (const float*)d_in[12];
    const float* Wtp    = (const float*)d_in[13];
    const float* btp    = (const float*)d_in[14];
    const float* Wsl    = (const float*)d_in[15];
    const float* bsl    = (const float*)d_in[16];
    float* outp = (float*)d_out;

    const int SM_PRE32 = 2 * 8 * 32 * 4;   // 2048

    cudaFuncSetAttribute(recurrent_kernel,
                         cudaFuncAttributeMaxDynamicSharedMemorySize, REC_SMEM);
    cudaFuncSetAttribute(precompute_mma_kernel,
                         cudaFuncAttributeMaxDynamicSharedMemorySize, PRE_SMEM);

    // layer 0
    precompute_kernel<32><<<148, 512, SM_PRE32>>>(x, Wih0, bih0, bhh0);
    recurrent_kernel<<<128, 512, REC_SMEM>>>(Whh0, /*out=A*/0, /*layer*/0);
    // layer 1 (in A -> out B)
    precompute_mma_kernel<<<148, 512, PRE_SMEM>>>(Wih123 + 0 * G4 * HID, 0,
        bih123 + 0 * G4, bhh123 + 0 * G4);
    recurrent_kernel<<<128, 512, REC_SMEM>>>(Whh123 + 0 * G4 * HID, 1, 1);
    // layer 2 (in B -> out A)
    precompute_mma_kernel<<<148, 512, PRE_SMEM>>>(Wih123 + 1 * G4 * HID, 1,
        bih123 + 1 * G4, bhh123 + 1 * G4);
    recurrent_kernel<<<128, 512, REC_SMEM>>>(Whh123 + 1 * G4 * HID, 0, 2);
    // layer 3 (in A -> out B)
    precompute_mma_kernel<<<148, 512, PRE_SMEM>>>(Wih123 + 2 * G4 * HID, 0,
        bih123 + 2 * G4, bhh123 + 2 * G4);
    recurrent_kernel<<<128, 512, REC_SMEM>>>(Whh123 + 2 * G4 * HID, 1, 3);
    // heads
    heads_kernel<<<(4 * 2048 + 255) / 256, 256>>>(
        Wopt, bopt, Wlot, blot, Wtp, btp, Wsl, bsl, outp);
}